// round 1
// baseline (speedup 1.0000x reference)
#include <cuda_runtime.h>
#include <cuda_bf16.h>

// Problem constants
#define B_   2
#define S_   2048
#define E_   1024
#define H_   16
#define HD_  64
#define M_   (B_ * S_)   // 4096 flattened rows

// Scratch (static device globals: allowed; runtime allocation is not)
__device__ float g_qh[M_ * E_];
__device__ float g_kh[M_ * E_];
__device__ float g_vh[M_ * E_];
__device__ float g_ah[M_ * E_];

#define FMA16(ACC, A4, B4)                                                     \
    do {                                                                       \
        ACC[0][0] += A4.x * B4.x; ACC[0][1] += A4.x * B4.y;                    \
        ACC[0][2] += A4.x * B4.z; ACC[0][3] += A4.x * B4.w;                    \
        ACC[1][0] += A4.y * B4.x; ACC[1][1] += A4.y * B4.y;                    \
        ACC[1][2] += A4.y * B4.z; ACC[1][3] += A4.y * B4.w;                    \
        ACC[2][0] += A4.z * B4.x; ACC[2][1] += A4.z * B4.y;                    \
        ACC[2][2] += A4.z * B4.z; ACC[2][3] += A4.z * B4.w;                    \
        ACC[3][0] += A4.w * B4.x; ACC[3][1] += A4.w * B4.y;                    \
        ACC[3][2] += A4.w * B4.z; ACC[3][3] += A4.w * B4.w;                    \
    } while (0)

// ---------------------------------------------------------------------------
// C[M,N] = A[M,K] @ W[N,K]^T (+ bias[N])        (torch Linear convention)
// 64x64 tile per CTA, TK=16, 256 threads, 4x4 per thread.
// ---------------------------------------------------------------------------
__global__ __launch_bounds__(256) void gemm_nt_kernel(
    const float* __restrict__ A, const float* __restrict__ W,
    const float* __restrict__ bias, float* __restrict__ C,
    int M, int N, int K)
{
    __shared__ float As[16][64];   // [k][m]
    __shared__ float Ws[16][64];   // [k][n]

    const int tid = threadIdx.x;
    const int tx = tid & 15;
    const int ty = tid >> 4;
    const int m0 = blockIdx.y << 6;
    const int n0 = blockIdx.x << 6;

    const int lrow = tid >> 2;          // 0..63
    const int lk   = (tid & 3) << 2;    // 0,4,8,12
    const float* Ag = A + (size_t)(m0 + lrow) * K + lk;
    const float* Wg = W + (size_t)(n0 + lrow) * K + lk;

    float acc[4][4] = {};

    for (int k0 = 0; k0 < K; k0 += 16) {
        float4 av = *(const float4*)(Ag + k0);
        float4 wv = *(const float4*)(Wg + k0);
        __syncthreads();  // WAR: previous chunk's compute done before overwrite
        As[lk + 0][lrow] = av.x; As[lk + 1][lrow] = av.y;
        As[lk + 2][lrow] = av.z; As[lk + 3][lrow] = av.w;
        Ws[lk + 0][lrow] = wv.x; Ws[lk + 1][lrow] = wv.y;
        Ws[lk + 2][lrow] = wv.z; Ws[lk + 3][lrow] = wv.w;
        __syncthreads();
        #pragma unroll
        for (int kk = 0; kk < 16; kk++) {
            float4 a4 = *(const float4*)&As[kk][ty << 2];
            float4 b4 = *(const float4*)&Ws[kk][tx << 2];
            FMA16(acc, a4, b4);
        }
    }

    #pragma unroll
    for (int i = 0; i < 4; i++) {
        const int row = m0 + (ty << 2) + i;
        const int col = n0 + (tx << 2);
        float4 r = make_float4(acc[i][0], acc[i][1], acc[i][2], acc[i][3]);
        if (bias) {
            const float4 bb = *(const float4*)&bias[col];
            r.x += bb.x; r.y += bb.y; r.z += bb.z; r.w += bb.w;
        }
        *(float4*)&C[(size_t)row * N + col] = r;
    }
}

// ---------------------------------------------------------------------------
// Flash attention, fp32, strict-causal (t < s) with (0,0) exception.
// One CTA = one (b,h) and a 64-row query tile; stream 64-key tiles.
// 256 threads as 16x16; each thread owns a 4x4 score tile and a 4x4 out tile.
// ---------------------------------------------------------------------------
__global__ __launch_bounds__(256) void attn_kernel(
    const float* __restrict__ QH, const float* __restrict__ KH,
    const float* __restrict__ VH, float* __restrict__ AH)
{
    __shared__ float Qs [64][64];   // [d][row]      (transposed)
    __shared__ float KPs[64][64];   // K: [d][col] -> reused as P: [t][row]
    __shared__ float Vs [64][64];   // [t][d]

    const int tid = threadIdx.x;
    const int tx = tid & 15;
    const int ty = tid >> 4;
    const int qi = blockIdx.x;            // query tile index (0..31)
    const int b  = blockIdx.y >> 4;
    const int h  = blockIdx.y & 15;
    const int s0 = qi << 6;
    const float scale = 0.125f;           // 1/sqrt(64)

    // Load Q tile transposed: Qs[d][r]
    {
        const int r = tid >> 2;
        #pragma unroll
        for (int ii = 0; ii < 4; ii++) {
            const int d = ((tid & 3) << 2) | (ii << 4);
            float4 v = *(const float4*)&QH[(size_t)(b * S_ + s0 + r) * E_ + h * HD_ + d];
            Qs[d + 0][r] = v.x; Qs[d + 1][r] = v.y;
            Qs[d + 2][r] = v.z; Qs[d + 3][r] = v.w;
        }
    }

    float o[4][4] = {};
    float m_run[4] = {-1e30f, -1e30f, -1e30f, -1e30f};
    float l_run[4] = {};

    for (int ti = 0; ti <= qi; ti++) {
        const int t0 = ti << 6;
        __syncthreads();  // previous iteration's P/V reads done (also covers Qs on iter 0)
        // Load K (transposed -> KPs[d][t]) and V (straight -> Vs[t][d])
        {
            const int tr = tid >> 2;
            #pragma unroll
            for (int ii = 0; ii < 4; ii++) {
                const int d = ((tid & 3) << 2) | (ii << 4);
                const size_t gro = (size_t)(b * S_ + t0 + tr) * E_ + h * HD_ + d;
                float4 kv = *(const float4*)&KH[gro];
                KPs[d + 0][tr] = kv.x; KPs[d + 1][tr] = kv.y;
                KPs[d + 2][tr] = kv.z; KPs[d + 3][tr] = kv.w;
                float4 vv = *(const float4*)&VH[gro];
                *(float4*)&Vs[tr][d] = vv;
            }
        }
        __syncthreads();

        // Scores: sc[i][j] = q(r0+i) . k(c0+j)
        float sc[4][4] = {};
        #pragma unroll
        for (int d = 0; d < 64; d++) {
            float4 a4 = *(const float4*)&Qs[d][ty << 2];
            float4 b4 = *(const float4*)&KPs[d][tx << 2];
            FMA16(sc, a4, b4);
        }

        // Scale + mask (diagonal tile only; ti<qi tiles are fully allowed)
        const bool diag = (ti == qi);
        #pragma unroll
        for (int i = 0; i < 4; i++) {
            #pragma unroll
            for (int j = 0; j < 4; j++) {
                float sval = sc[i][j] * scale;
                if (diag) {
                    const int r = (ty << 2) + i;
                    const int c = (tx << 2) + j;
                    const bool allowed = (c < r) || (qi == 0 && r == 0 && c == 0);
                    if (!allowed) sval = -1e30f;
                }
                sc[i][j] = sval;
            }
        }

        // Online softmax (row groups live on 16-lane half-warps: lanes share ty)
        #pragma unroll
        for (int i = 0; i < 4; i++) {
            float v = fmaxf(fmaxf(sc[i][0], sc[i][1]), fmaxf(sc[i][2], sc[i][3]));
            #pragma unroll
            for (int off = 1; off < 16; off <<= 1)
                v = fmaxf(v, __shfl_xor_sync(0xffffffffu, v, off));
            const float mnew = fmaxf(m_run[i], v);
            sc[i][0] = __expf(sc[i][0] - mnew);
            sc[i][1] = __expf(sc[i][1] - mnew);
            sc[i][2] = __expf(sc[i][2] - mnew);
            sc[i][3] = __expf(sc[i][3] - mnew);
            float rs = sc[i][0] + sc[i][1] + sc[i][2] + sc[i][3];
            #pragma unroll
            for (int off = 1; off < 16; off <<= 1)
                rs += __shfl_xor_sync(0xffffffffu, rs, off);
            const float alpha = __expf(m_run[i] - mnew);
            l_run[i] = l_run[i] * alpha + rs;
            m_run[i] = mnew;
            #pragma unroll
            for (int j = 0; j < 4; j++) o[i][j] *= alpha;
        }

        // P into smem (transposed: KPs[t][r]), reusing the K buffer
        __syncthreads();  // everyone done reading K data from KPs
        #pragma unroll
        for (int i = 0; i < 4; i++)
            #pragma unroll
            for (int j = 0; j < 4; j++)
                KPs[(tx << 2) + j][(ty << 2) + i] = sc[i][j];
        __syncthreads();

        // O += P @ V
        #pragma unroll
        for (int t = 0; t < 64; t++) {
            float4 p4 = *(const float4*)&KPs[t][ty << 2];
            float4 v4 = *(const float4*)&Vs[t][tx << 2];
            FMA16(o, p4, v4);
        }
    }

    // Normalize and write out: AH[(b,s), h*64+d]
    #pragma unroll
    for (int i = 0; i < 4; i++) {
        const float inv = 1.0f / l_run[i];
        const int row = b * S_ + s0 + (ty << 2) + i;
        float4 r = make_float4(o[i][0] * inv, o[i][1] * inv,
                               o[i][2] * inv, o[i][3] * inv);
        *(float4*)&AH[(size_t)row * E_ + h * HD_ + (tx << 2)] = r;
    }
}

// ---------------------------------------------------------------------------
extern "C" void kernel_launch(void* const* d_in, const int* in_sizes, int n_in,
                              void* d_out, int out_size)
{
    const float* q  = (const float*)d_in[0];
    const float* k  = (const float*)d_in[1];
    const float* v  = (const float*)d_in[2];
    const float* Wq = (const float*)d_in[3];
    const float* Wk = (const float*)d_in[4];
    const float* Wv = (const float*)d_in[5];
    const float* bv = (const float*)d_in[6];
    const float* Wo = (const float*)d_in[7];
    const float* bo = (const float*)d_in[8];
    float* out = (float*)d_out;

    float *qh, *kh, *vh, *ah;
    cudaGetSymbolAddress((void**)&qh, g_qh);
    cudaGetSymbolAddress((void**)&kh, g_kh);
    cudaGetSymbolAddress((void**)&vh, g_vh);
    cudaGetSymbolAddress((void**)&ah, g_ah);

    const dim3 gblk(256);
    const dim3 ggrd(E_ / 64, M_ / 64);       // (16, 64)

    gemm_nt_kernel<<<ggrd, gblk>>>(q, Wq, nullptr, qh, M_, E_, E_);
    gemm_nt_kernel<<<ggrd, gblk>>>(k, Wk, nullptr, kh, M_, E_, E_);
    gemm_nt_kernel<<<ggrd, gblk>>>(v, Wv, bv,      vh, M_, E_, E_);

    const dim3 agrd(S_ / 64, B_ * H_);       // (32, 32)
    attn_kernel<<<agrd, gblk>>>(qh, kh, vh, ah);

    gemm_nt_kernel<<<ggrd, gblk>>>(ah, Wo, bo, out, M_, E_, E_);
}

// round 3
// speedup vs baseline: 1.7437x; 1.7437x over previous
#include <cuda_runtime.h>
#include <cstdint>

// Problem constants
#define B_   2
#define S_   2048
#define E_   1024
#define H_   16
#define HD_  64
#define M_   (B_ * S_)   // 4096 flattened rows

// Scratch (static device globals: allowed; runtime allocation is not)
__device__ float g_qh[M_ * E_];
__device__ float g_kh[M_ * E_];
__device__ float g_vh[M_ * E_];
__device__ float g_ah[M_ * E_];
__device__ float g_qr[M_ * E_];        // tf32-rounded activations
__device__ float g_kr[M_ * E_];
__device__ float g_vr[M_ * E_];
__device__ float g_wr[4 * E_ * E_];    // tf32-rounded Wq,Wk,Wv,Wo

// ===========================================================================
// Helpers
// ===========================================================================
__device__ __forceinline__ uint32_t smem_u32(const void* p) {
    uint32_t a;
    asm("{ .reg .u64 t; cvta.to.shared.u64 t, %1; cvt.u32.u64 %0, t; }"
        : "=r"(a) : "l"(p));
    return a;
}

__device__ __forceinline__ float to_tf32(float x) {
    uint32_t u;
    asm("cvt.rna.tf32.f32 %0, %1;" : "=r"(u) : "f"(x));
    return __uint_as_float(u);
}

__device__ __forceinline__ void cp_async16(uint32_t dst, const void* src) {
    asm volatile("cp.async.cg.shared.global [%0], [%1], 16;"
                 :: "r"(dst), "l"(src) : "memory");
}
#define CP_COMMIT() asm volatile("cp.async.commit_group;" ::: "memory")
#define CP_WAIT1()  asm volatile("cp.async.wait_group 1;" ::: "memory")

__device__ __forceinline__ void mma_tf32(float* d, const uint32_t* a, const uint32_t* b) {
    asm volatile(
        "mma.sync.aligned.m16n8k8.row.col.f32.tf32.tf32.f32 "
        "{%0,%1,%2,%3}, {%4,%5,%6,%7}, {%8,%9}, {%0,%1,%2,%3};"
        : "+f"(d[0]), "+f"(d[1]), "+f"(d[2]), "+f"(d[3])
        : "r"(a[0]), "r"(a[1]), "r"(a[2]), "r"(a[3]), "r"(b[0]), "r"(b[1]));
}

// ===========================================================================
// tf32 rounding prepass
// ===========================================================================
__global__ __launch_bounds__(256) void round_tf32_kernel(
    const float* __restrict__ in, float* __restrict__ out, int n4)
{
    const int i = (blockIdx.x * 256 + threadIdx.x);
    if (i < n4) {
        float4 v = *(const float4*)(in + i * 4);
        v.x = to_tf32(v.x); v.y = to_tf32(v.y);
        v.z = to_tf32(v.z); v.w = to_tf32(v.w);
        *(float4*)(out + i * 4) = v;
    }
}

// ===========================================================================
// mma.sync tf32 GEMM:  C[M,1024] = A[M,1024] @ W[1024,1024]^T (+ bias)
// CTA 128x256, 8 warps (2x4), warp tile 64x64, K-chunk 32, 3-stage cp.async.
// Smem row stride 36 floats -> conflict-free fragment gathers.
// blockIdx.z selects problem (fused Q/K projections).
// ===========================================================================
#define GTM   128
#define GTN   256
#define GTK   32
#define NCH   (E_ / GTK)                  // 32
#define LDS_  36
#define STG_FLOATS ((GTM + GTN) * LDS_)   // 13824
#define STG_BYTES  (STG_FLOATS * 4)       // 55296
#define NSTG  3
#define GEMM_SMEM (NSTG * STG_BYTES)      // 165888

__global__ __launch_bounds__(256, 1) void gemm_mma(
    const float* __restrict__ A0, const float* __restrict__ A1,
    const float* __restrict__ W0, const float* __restrict__ W1,
    float* __restrict__ C0, float* __restrict__ C1,
    const float* __restrict__ bias)
{
    extern __shared__ float smem[];
    const int tid  = threadIdx.x;
    const int lane = tid & 31;
    const int wid  = tid >> 5;
    const int wm   = wid >> 2;   // 0..1  (64 rows each)
    const int wn   = wid & 3;    // 0..3  (64 cols each)

    const float* A = blockIdx.z ? A1 : A0;
    const float* W = blockIdx.z ? W1 : W0;
    float*       C = blockIdx.z ? C1 : C0;

    const int m0 = blockIdx.x * GTM;
    const int n0 = blockIdx.y * GTN;
    const uint32_t sb = smem_u32(smem);

    float acc[4][8][4] = {};

    // ---- async chunk loader: A 128x32, W 256x32 into padded smem ----
    auto load_chunk = [&](int ch, int stg) {
        const int k0 = ch * GTK;
        const uint32_t as = sb + stg * STG_BYTES;
        const uint32_t bs = as + GTM * LDS_ * 4;
        #pragma unroll
        for (int it = 0; it < 4; it++) {
            const int idx = tid + it * 256;
            const int r = idx >> 3, c4 = idx & 7;
            cp_async16(as + r * (LDS_ * 4) + c4 * 16,
                       A + (size_t)(m0 + r) * E_ + k0 + c4 * 4);
        }
        #pragma unroll
        for (int it = 0; it < 8; it++) {
            const int idx = tid + it * 256;
            const int r = idx >> 3, c4 = idx & 7;
            cp_async16(bs + r * (LDS_ * 4) + c4 * 16,
                       W + (size_t)(n0 + r) * E_ + k0 + c4 * 4);
        }
    };

    load_chunk(0, 0); CP_COMMIT();
    load_chunk(1, 1); CP_COMMIT();

    const int g = lane >> 2;   // group id (row within fragment)
    const int c = lane & 3;    // thread-in-group (k within fragment)

    for (int i = 0; i < NCH; i++) {
        CP_WAIT1();
        __syncthreads();
        if (i + 2 < NCH) load_chunk(i + 2, (i + 2) % NSTG);
        CP_COMMIT();   // always commit (keeps wait_group accounting exact)

        const float* as = smem + (i % NSTG) * STG_FLOATS;
        const float* bs = as + GTM * LDS_;

        #pragma unroll
        for (int kk = 0; kk < 4; kk++) {
            const int k8 = kk * 8;
            uint32_t af[4][4], bf[8][2];
            #pragma unroll
            for (int ii = 0; ii < 4; ii++) {
                const int r = wm * 64 + ii * 16 + g;
                af[ii][0] = __float_as_uint(as[r * LDS_ + k8 + c]);
                af[ii][1] = __float_as_uint(as[(r + 8) * LDS_ + k8 + c]);
                af[ii][2] = __float_as_uint(as[r * LDS_ + k8 + c + 4]);
                af[ii][3] = __float_as_uint(as[(r + 8) * LDS_ + k8 + c + 4]);
            }
            #pragma unroll
            for (int jj = 0; jj < 8; jj++) {
                const int n = wn * 64 + jj * 8 + g;
                bf[jj][0] = __float_as_uint(bs[n * LDS_ + k8 + c]);
                bf[jj][1] = __float_as_uint(bs[n * LDS_ + k8 + c + 4]);
            }
            #pragma unroll
            for (int ii = 0; ii < 4; ii++)
                #pragma unroll
                for (int jj = 0; jj < 8; jj++)
                    mma_tf32(acc[ii][jj], af[ii], bf[jj]);
        }
    }

    // ---- epilogue: fragment layout -> global fp32, optional bias ----
    #pragma unroll
    for (int ii = 0; ii < 4; ii++) {
        const int r0 = m0 + wm * 64 + ii * 16 + g;
        #pragma unroll
        for (int jj = 0; jj < 8; jj++) {
            const int cc = n0 + wn * 64 + jj * 8 + 2 * c;
            float bx = 0.f, by = 0.f;
            if (bias) { bx = bias[cc]; by = bias[cc + 1]; }
            float2 v0 = make_float2(acc[ii][jj][0] + bx, acc[ii][jj][1] + by);
            float2 v1 = make_float2(acc[ii][jj][2] + bx, acc[ii][jj][3] + by);
            *(float2*)&C[(size_t)r0 * E_ + cc]       = v0;
            *(float2*)&C[(size_t)(r0 + 8) * E_ + cc] = v1;
        }
    }
}

// ===========================================================================
// Flash attention, fp32, strict-causal (t < s) with (0,0) exception.
// (unchanged except: output rounded to tf32 for the Wo GEMM)
// ===========================================================================
#define FMA16(ACC, A4, B4)                                                     \
    do {                                                                       \
        ACC[0][0] += A4.x * B4.x; ACC[0][1] += A4.x * B4.y;                    \
        ACC[0][2] += A4.x * B4.z; ACC[0][3] += A4.x * B4.w;                    \
        ACC[1][0] += A4.y * B4.x; ACC[1][1] += A4.y * B4.y;                    \
        ACC[1][2] += A4.y * B4.z; ACC[1][3] += A4.y * B4.w;                    \
        ACC[2][0] += A4.z * B4.x; ACC[2][1] += A4.z * B4.y;                    \
        ACC[2][2] += A4.z * B4.z; ACC[2][3] += A4.z * B4.w;                    \
        ACC[3][0] += A4.w * B4.x; ACC[3][1] += A4.w * B4.y;                    \
        ACC[3][2] += A4.w * B4.z; ACC[3][3] += A4.w * B4.w;                    \
    } while (0)

__global__ __launch_bounds__(256) void attn_kernel(
    const float* __restrict__ QH, const float* __restrict__ KH,
    const float* __restrict__ VH, float* __restrict__ AH)
{
    __shared__ float Qs [64][64];
    __shared__ float KPs[64][64];
    __shared__ float Vs [64][64];

    const int tid = threadIdx.x;
    const int tx = tid & 15;
    const int ty = tid >> 4;
    const int qi = blockIdx.x;
    const int b  = blockIdx.y >> 4;
    const int h  = blockIdx.y & 15;
    const int s0 = qi << 6;
    const float scale = 0.125f;

    {
        const int r = tid >> 2;
        #pragma unroll
        for (int ii = 0; ii < 4; ii++) {
            const int d = ((tid & 3) << 2) | (ii << 4);
            float4 v = *(const float4*)&QH[(size_t)(b * S_ + s0 + r) * E_ + h * HD_ + d];
            Qs[d + 0][r] = v.x; Qs[d + 1][r] = v.y;
            Qs[d + 2][r] = v.z; Qs[d + 3][r] = v.w;
        }
    }

    float o[4][4] = {};
    float m_run[4] = {-1e30f, -1e30f, -1e30f, -1e30f};
    float l_run[4] = {};

    for (int ti = 0; ti <= qi; ti++) {
        const int t0 = ti << 6;
        __syncthreads();
        {
            const int tr = tid >> 2;
            #pragma unroll
            for (int ii = 0; ii < 4; ii++) {
                const int d = ((tid & 3) << 2) | (ii << 4);
                const size_t gro = (size_t)(b * S_ + t0 + tr) * E_ + h * HD_ + d;
                float4 kv = *(const float4*)&KH[gro];
                KPs[d + 0][tr] = kv.x; KPs[d + 1][tr] = kv.y;
                KPs[d + 2][tr] = kv.z; KPs[d + 3][tr] = kv.w;
                float4 vv = *(const float4*)&VH[gro];
                *(float4*)&Vs[tr][d] = vv;
            }
        }
        __syncthreads();

        float sc[4][4] = {};
        #pragma unroll
        for (int d = 0; d < 64; d++) {
            float4 a4 = *(const float4*)&Qs[d][ty << 2];
            float4 b4 = *(const float4*)&KPs[d][tx << 2];
            FMA16(sc, a4, b4);
        }

        const bool diag = (ti == qi);
        #pragma unroll
        for (int i = 0; i < 4; i++) {
            #pragma unroll
            for (int j = 0; j < 4; j++) {
                float sval = sc[i][j] * scale;
                if (diag) {
                    const int r = (ty << 2) + i;
                    const int cix = (tx << 2) + j;
                    const bool allowed = (cix < r) || (qi == 0 && r == 0 && cix == 0);
                    if (!allowed) sval = -1e30f;
                }
                sc[i][j] = sval;
            }
        }

        #pragma unroll
        for (int i = 0; i < 4; i++) {
            float v = fmaxf(fmaxf(sc[i][0], sc[i][1]), fmaxf(sc[i][2], sc[i][3]));
            #pragma unroll
            for (int off = 1; off < 16; off <<= 1)
                v = fmaxf(v, __shfl_xor_sync(0xffffffffu, v, off));
            const float mnew = fmaxf(m_run[i], v);
            sc[i][0] = __expf(sc[i][0] - mnew);
            sc[i][1] = __expf(sc[i][1] - mnew);
            sc[i][2] = __expf(sc[i][2] - mnew);
            sc[i][3] = __expf(sc[i][3] - mnew);
            float rs = sc[i][0] + sc[i][1] + sc[i][2] + sc[i][3];
            #pragma unroll
            for (int off = 1; off < 16; off <<= 1)
                rs += __shfl_xor_sync(0xffffffffu, rs, off);
            const float alpha = __expf(m_run[i] - mnew);
            l_run[i] = l_run[i] * alpha + rs;
            m_run[i] = mnew;
            #pragma unroll
            for (int j = 0; j < 4; j++) o[i][j] *= alpha;
        }

        __syncthreads();
        #pragma unroll
        for (int i = 0; i < 4; i++)
            #pragma unroll
            for (int j = 0; j < 4; j++)
                KPs[(tx << 2) + j][(ty << 2) + i] = sc[i][j];
        __syncthreads();

        #pragma unroll
        for (int t = 0; t < 64; t++) {
            float4 p4 = *(const float4*)&KPs[t][ty << 2];
            float4 v4 = *(const float4*)&Vs[t][tx << 2];
            FMA16(o, p4, v4);
        }
    }

    #pragma unroll
    for (int i = 0; i < 4; i++) {
        const float inv = 1.0f / l_run[i];
        const int row = b * S_ + s0 + (ty << 2) + i;
        float4 r = make_float4(to_tf32(o[i][0] * inv), to_tf32(o[i][1] * inv),
                               to_tf32(o[i][2] * inv), to_tf32(o[i][3] * inv));
        *(float4*)&AH[(size_t)row * E_ + h * HD_ + (tx << 2)] = r;
    }
}

// ===========================================================================
extern "C" void kernel_launch(void* const* d_in, const int* in_sizes, int n_in,
                              void* d_out, int out_size)
{
    const float* q  = (const float*)d_in[0];
    const float* k  = (const float*)d_in[1];
    const float* v  = (const float*)d_in[2];
    const float* Wq = (const float*)d_in[3];
    const float* Wk = (const float*)d_in[4];
    const float* Wv = (const float*)d_in[5];
    const float* bv = (const float*)d_in[6];
    const float* Wo = (const float*)d_in[7];
    const float* bo = (const float*)d_in[8];
    float* out = (float*)d_out;

    float *qh, *kh, *vh, *ah, *qr, *kr, *vr, *wr;
    cudaGetSymbolAddress((void**)&qh, g_qh);
    cudaGetSymbolAddress((void**)&kh, g_kh);
    cudaGetSymbolAddress((void**)&vh, g_vh);
    cudaGetSymbolAddress((void**)&ah, g_ah);
    cudaGetSymbolAddress((void**)&qr, g_qr);
    cudaGetSymbolAddress((void**)&kr, g_kr);
    cudaGetSymbolAddress((void**)&vr, g_vr);
    cudaGetSymbolAddress((void**)&wr, g_wr);

    cudaFuncSetAttribute(gemm_mma, cudaFuncAttributeMaxDynamicSharedMemorySize,
                         GEMM_SMEM);

    // ---- tf32 prepass: activations + weights ----
    const int n4_act = (M_ * E_) / 4;        // 1M float4
    const int n4_w   = (E_ * E_) / 4;        // 256K float4
    round_tf32_kernel<<<(n4_act + 255) / 256, 256>>>(q, qr, n4_act);
    round_tf32_kernel<<<(n4_act + 255) / 256, 256>>>(k, kr, n4_act);
    round_tf32_kernel<<<(n4_act + 255) / 256, 256>>>(v, vr, n4_act);
    round_tf32_kernel<<<(n4_w + 255) / 256, 256>>>(Wq, wr + 0 * E_ * E_, n4_w);
    round_tf32_kernel<<<(n4_w + 255) / 256, 256>>>(Wk, wr + 1 * E_ * E_, n4_w);
    round_tf32_kernel<<<(n4_w + 255) / 256, 256>>>(Wv, wr + 2 * E_ * E_, n4_w);
    round_tf32_kernel<<<(n4_w + 255) / 256, 256>>>(Wo, wr + 3 * E_ * E_, n4_w);

    // ---- projections ----
    const dim3 ggrd1(M_ / GTM, E_ / GTN, 1);   // (32, 4)
    const dim3 ggrd2(M_ / GTM, E_ / GTN, 2);   // fused Q+K
    gemm_mma<<<ggrd2, 256, GEMM_SMEM>>>(qr, kr, wr, wr + E_ * E_, qh, kh, nullptr);
    gemm_mma<<<ggrd1, 256, GEMM_SMEM>>>(vr, vr, wr + 2 * E_ * E_, nullptr, vh, nullptr, bv);

    // ---- attention ----
    const dim3 agrd(S_ / 64, B_ * H_);         // (32, 32)
    attn_kernel<<<agrd, 256>>>(qh, kh, vh, ah);

    // ---- output projection ----
    gemm_mma<<<ggrd1, 256, GEMM_SMEM>>>(ah, ah, wr + 3 * E_ * E_, nullptr, out, nullptr, bo);
}

// round 4
// speedup vs baseline: 4.0129x; 2.3014x over previous
#include <cuda_runtime.h>
#include <cstdint>

// Problem constants
#define B_   2
#define S_   2048
#define E_   1024
#define H_   16
#define HD_  64
#define M_   (B_ * S_)   // 4096 flattened rows

// Scratch
__device__ float g_qh[M_ * E_];
__device__ float g_kh[M_ * E_];
__device__ float g_vh[M_ * E_];
__device__ float g_ah[M_ * E_];
__device__ float g_qr[M_ * E_];        // tf32-rounded activations
__device__ float g_kr[M_ * E_];
__device__ float g_vr[M_ * E_];
__device__ float g_wr[4 * E_ * E_];    // tf32-rounded Wq,Wk,Wv,Wo

// ===========================================================================
// Helpers
// ===========================================================================
__device__ __forceinline__ uint32_t smem_u32(const void* p) {
    uint32_t a;
    asm("{ .reg .u64 t; cvta.to.shared.u64 t, %1; cvt.u32.u64 %0, t; }"
        : "=r"(a) : "l"(p));
    return a;
}

__device__ __forceinline__ float to_tf32(float x) {
    uint32_t u;
    asm("cvt.rna.tf32.f32 %0, %1;" : "=r"(u) : "f"(x));
    return __uint_as_float(u);
}

__device__ __forceinline__ void cp_async16(uint32_t dst, const void* src) {
    asm volatile("cp.async.cg.shared.global [%0], [%1], 16;"
                 :: "r"(dst), "l"(src) : "memory");
}
#define CP_COMMIT() asm volatile("cp.async.commit_group;" ::: "memory")
#define CP_WAIT1()  asm volatile("cp.async.wait_group 1;" ::: "memory")

__device__ __forceinline__ void mma_tf32(float* d, const uint32_t* a, const uint32_t* b) {
    asm volatile(
        "mma.sync.aligned.m16n8k8.row.col.f32.tf32.tf32.f32 "
        "{%0,%1,%2,%3}, {%4,%5,%6,%7}, {%8,%9}, {%0,%1,%2,%3};"
        : "+f"(d[0]), "+f"(d[1]), "+f"(d[2]), "+f"(d[3])
        : "r"(a[0]), "r"(a[1]), "r"(a[2]), "r"(a[3]), "r"(b[0]), "r"(b[1]));
}

// ===========================================================================
// tf32 rounding prepass
// ===========================================================================
__global__ __launch_bounds__(256) void round_tf32_kernel(
    const float* __restrict__ in, float* __restrict__ out, int n4)
{
    const int i = (blockIdx.x * 256 + threadIdx.x);
    if (i < n4) {
        float4 v = *(const float4*)(in + i * 4);
        v.x = to_tf32(v.x); v.y = to_tf32(v.y);
        v.z = to_tf32(v.z); v.w = to_tf32(v.w);
        *(float4*)(out + i * 4) = v;
    }
}

// ===========================================================================
// mma.sync tf32 GEMM:  C[M,1024] = A[M,1024] @ W[1024,1024]^T (+ bias)
// round_out: RN-round result to tf32 (for GEMMs feeding later tf32 mmas).
// ===========================================================================
#define GTM   128
#define GTN   256
#define GTK   32
#define NCH   (E_ / GTK)
#define LDS_  36
#define STG_FLOATS ((GTM + GTN) * LDS_)
#define STG_BYTES  (STG_FLOATS * 4)
#define NSTG  3
#define GEMM_SMEM (NSTG * STG_BYTES)

__global__ __launch_bounds__(256, 1) void gemm_mma(
    const float* __restrict__ A0, const float* __restrict__ A1,
    const float* __restrict__ W0, const float* __restrict__ W1,
    float* __restrict__ C0, float* __restrict__ C1,
    const float* __restrict__ bias, int round_out)
{
    extern __shared__ float smem[];
    const int tid  = threadIdx.x;
    const int lane = tid & 31;
    const int wid  = tid >> 5;
    const int wm   = wid >> 2;
    const int wn   = wid & 3;

    const float* A = blockIdx.z ? A1 : A0;
    const float* W = blockIdx.z ? W1 : W0;
    float*       C = blockIdx.z ? C1 : C0;

    const int m0 = blockIdx.x * GTM;
    const int n0 = blockIdx.y * GTN;
    const uint32_t sb = smem_u32(smem);

    float acc[4][8][4] = {};

    auto load_chunk = [&](int ch, int stg) {
        const int k0 = ch * GTK;
        const uint32_t as = sb + stg * STG_BYTES;
        const uint32_t bs = as + GTM * LDS_ * 4;
        #pragma unroll
        for (int it = 0; it < 4; it++) {
            const int idx = tid + it * 256;
            const int r = idx >> 3, c4 = idx & 7;
            cp_async16(as + r * (LDS_ * 4) + c4 * 16,
                       A + (size_t)(m0 + r) * E_ + k0 + c4 * 4);
        }
        #pragma unroll
        for (int it = 0; it < 8; it++) {
            const int idx = tid + it * 256;
            const int r = idx >> 3, c4 = idx & 7;
            cp_async16(bs + r * (LDS_ * 4) + c4 * 16,
                       W + (size_t)(n0 + r) * E_ + k0 + c4 * 4);
        }
    };

    load_chunk(0, 0); CP_COMMIT();
    load_chunk(1, 1); CP_COMMIT();

    const int g = lane >> 2;
    const int c = lane & 3;

    for (int i = 0; i < NCH; i++) {
        CP_WAIT1();
        __syncthreads();
        if (i + 2 < NCH) load_chunk(i + 2, (i + 2) % NSTG);
        CP_COMMIT();

        const float* as = smem + (i % NSTG) * STG_FLOATS;
        const float* bs = as + GTM * LDS_;

        #pragma unroll
        for (int kk = 0; kk < 4; kk++) {
            const int k8 = kk * 8;
            uint32_t af[4][4], bf[8][2];
            #pragma unroll
            for (int ii = 0; ii < 4; ii++) {
                const int r = wm * 64 + ii * 16 + g;
                af[ii][0] = __float_as_uint(as[r * LDS_ + k8 + c]);
                af[ii][1] = __float_as_uint(as[(r + 8) * LDS_ + k8 + c]);
                af[ii][2] = __float_as_uint(as[r * LDS_ + k8 + c + 4]);
                af[ii][3] = __float_as_uint(as[(r + 8) * LDS_ + k8 + c + 4]);
            }
            #pragma unroll
            for (int jj = 0; jj < 8; jj++) {
                const int n = wn * 64 + jj * 8 + g;
                bf[jj][0] = __float_as_uint(bs[n * LDS_ + k8 + c]);
                bf[jj][1] = __float_as_uint(bs[n * LDS_ + k8 + c + 4]);
            }
            #pragma unroll
            for (int ii = 0; ii < 4; ii++)
                #pragma unroll
                for (int jj = 0; jj < 8; jj++)
                    mma_tf32(acc[ii][jj], af[ii], bf[jj]);
        }
    }

    #pragma unroll
    for (int ii = 0; ii < 4; ii++) {
        const int r0 = m0 + wm * 64 + ii * 16 + g;
        #pragma unroll
        for (int jj = 0; jj < 8; jj++) {
            const int cc = n0 + wn * 64 + jj * 8 + 2 * c;
            float bx = 0.f, by = 0.f;
            if (bias) { bx = bias[cc]; by = bias[cc + 1]; }
            float2 v0 = make_float2(acc[ii][jj][0] + bx, acc[ii][jj][1] + by);
            float2 v1 = make_float2(acc[ii][jj][2] + bx, acc[ii][jj][3] + by);
            if (round_out) {
                v0.x = to_tf32(v0.x); v0.y = to_tf32(v0.y);
                v1.x = to_tf32(v1.x); v1.y = to_tf32(v1.y);
            }
            *(float2*)&C[(size_t)r0 * E_ + cc]       = v0;
            *(float2*)&C[(size_t)(r0 + 8) * E_ + cc] = v1;
        }
    }
}

// ===========================================================================
// Tensor-core flash attention (tf32 mma), strict-causal with (0,0) exception.
// CTA = (b,h) x 128 q-rows; 8 warps x 16 rows; K/V blocks of 64, cp.async x2.
// ===========================================================================
#define AQ    128
#define AK    64
#define QSTR  68          // Q/K smem stride (floats): frag banks 4g+c, distinct
#define VSTR  72          // V/P smem stride (floats): frag banks 8c+g / 8g+c
#define KS_FLOATS (AK * QSTR)          // 4352
#define VS_FLOATS (AK * VSTR)          // 4608
#define QP_FLOATS (8 * 16 * VSTR)      // 9216 (>= 128*QSTR? no: Q needs 8704; P 9216)
#define OFF_K  QP_FLOATS               // 9216
#define OFF_V  (OFF_K + 2 * KS_FLOATS) // 17920
#define ATTN_SMEM ((OFF_V + 2 * VS_FLOATS) * 4)  // 27136 floats = 108544 B

__global__ __launch_bounds__(256, 1) void attn_mma(
    const float* __restrict__ QH, const float* __restrict__ KH,
    const float* __restrict__ VH, float* __restrict__ AH)
{
    extern __shared__ float sm[];
    const int tid  = threadIdx.x;
    const int lane = tid & 31;
    const int w    = tid >> 5;
    const int g    = lane >> 2;
    const int c    = lane & 3;
    const int qi   = (int)(gridDim.x - 1) - (int)blockIdx.x;  // heavy tiles first
    const int bh   = blockIdx.y;
    const int b    = bh >> 4;
    const int h    = bh & 15;
    const int qbase = qi * AQ;
    const size_t rb = (size_t)b * S_ * E_ + (size_t)h * HD_;

    float* Qs = sm;                       // Q tile [128][QSTR], then reused as P
    float* Ps = sm + w * (16 * VSTR);     // per-warp P tile [16][VSTR]
    const uint32_t sb = smem_u32(sm);

    // ---- load Q tile, gather Q fragments into registers ----
    #pragma unroll
    for (int it = 0; it < 8; it++) {
        const int idx = tid + it * 256;            // 2048 float4
        const int r = idx >> 4, c4 = idx & 15;
        float4 v = *(const float4*)&QH[rb + (size_t)(qbase + r) * E_ + c4 * 4];
        *(float4*)&Qs[r * QSTR + c4 * 4] = v;
    }
    __syncthreads();
    uint32_t qf[8][4];
    {
        const float* qw = Qs + (w * 16) * QSTR;
        #pragma unroll
        for (int kk = 0; kk < 8; kk++) {
            qf[kk][0] = __float_as_uint(qw[g * QSTR + kk * 8 + c]);
            qf[kk][1] = __float_as_uint(qw[(g + 8) * QSTR + kk * 8 + c]);
            qf[kk][2] = __float_as_uint(qw[g * QSTR + kk * 8 + c + 4]);
            qf[kk][3] = __float_as_uint(qw[(g + 8) * QSTR + kk * 8 + c + 4]);
        }
    }
    __syncthreads();  // Qs region becomes P region

    float o[8][4] = {};
    float m0 = -1e30f, m1 = -1e30f, l0 = 0.f, l1 = 0.f;
    const int nb = 2 * qi + 2;
    const int qrow0 = qbase + w * 16 + g;
    const int wmin  = qbase + w * 16;
    const int wmax  = wmin + 15;

    auto loadKV = [&](int kb, int stg) {
        const int t0 = kb * AK;
        const uint32_t ks = sb + (OFF_K + stg * KS_FLOATS) * 4;
        const uint32_t vs = sb + (OFF_V + stg * VS_FLOATS) * 4;
        #pragma unroll
        for (int it = 0; it < 4; it++) {
            const int idx = tid + it * 256;        // 1024 float4
            const int r = idx >> 4, c4 = idx & 15;
            cp_async16(ks + (r * QSTR + c4 * 4) * 4,
                       &KH[rb + (size_t)(t0 + r) * E_ + c4 * 4]);
            cp_async16(vs + (r * VSTR + c4 * 4) * 4,
                       &VH[rb + (size_t)(t0 + r) * E_ + c4 * 4]);
        }
    };

    loadKV(0, 0); CP_COMMIT();

    for (int kb = 0; kb < nb; kb++) {
        const int stg = kb & 1;
        const int t0  = kb * AK;
        if (kb + 1 < nb) loadKV(kb + 1, stg ^ 1);
        CP_COMMIT();
        CP_WAIT1();
        __syncthreads();

        if (t0 <= wmax) {   // warp has at least one unmasked row in this block
            const float* Ks = sm + OFF_K + stg * KS_FLOATS;
            const float* Vs = sm + OFF_V + stg * VS_FLOATS;

            // ---- S = Q @ K^T ----
            float sc[8][4] = {};
            #pragma unroll
            for (int kk = 0; kk < 8; kk++) {
                uint32_t bf[8][2];
                #pragma unroll
                for (int jj = 0; jj < 8; jj++) {
                    const int n = jj * 8 + g;
                    bf[jj][0] = __float_as_uint(Ks[n * QSTR + kk * 8 + c]);
                    bf[jj][1] = __float_as_uint(Ks[n * QSTR + kk * 8 + c + 4]);
                }
                #pragma unroll
                for (int jj = 0; jj < 8; jj++)
                    mma_tf32(sc[jj], qf[kk], bf[jj]);
            }

            // ---- scale + causal mask ----
            const bool needmask = (t0 + AK - 1) >= wmin;
            #pragma unroll
            for (int jj = 0; jj < 8; jj++) {
                sc[jj][0] *= 0.125f; sc[jj][1] *= 0.125f;
                sc[jj][2] *= 0.125f; sc[jj][3] *= 0.125f;
                if (needmask) {
                    const int cg = t0 + jj * 8 + 2 * c;
                    const int r0 = qrow0, r1 = qrow0 + 8;
                    if (!((cg     < r0) || (r0 == 0 && cg == 0)))     sc[jj][0] = -1e30f;
                    if (!((cg + 1 < r0) || (r0 == 0 && cg + 1 == 0))) sc[jj][1] = -1e30f;
                    if (!(cg     < r1)) sc[jj][2] = -1e30f;
                    if (!(cg + 1 < r1)) sc[jj][3] = -1e30f;
                }
            }

            // ---- online softmax (rows g / g+8; reduce across c lanes) ----
            float mx0 = -1e30f, mx1 = -1e30f;
            #pragma unroll
            for (int jj = 0; jj < 8; jj++) {
                mx0 = fmaxf(mx0, fmaxf(sc[jj][0], sc[jj][1]));
                mx1 = fmaxf(mx1, fmaxf(sc[jj][2], sc[jj][3]));
            }
            mx0 = fmaxf(mx0, __shfl_xor_sync(0xffffffffu, mx0, 1));
            mx0 = fmaxf(mx0, __shfl_xor_sync(0xffffffffu, mx0, 2));
            mx1 = fmaxf(mx1, __shfl_xor_sync(0xffffffffu, mx1, 1));
            mx1 = fmaxf(mx1, __shfl_xor_sync(0xffffffffu, mx1, 2));
            const float mn0 = fmaxf(m0, mx0), mn1 = fmaxf(m1, mx1);
            const float a0 = __expf(m0 - mn0), a1 = __expf(m1 - mn1);
            float s0 = 0.f, s1 = 0.f;
            #pragma unroll
            for (int jj = 0; jj < 8; jj++) {
                sc[jj][0] = __expf(sc[jj][0] - mn0);
                sc[jj][1] = __expf(sc[jj][1] - mn0);
                sc[jj][2] = __expf(sc[jj][2] - mn1);
                sc[jj][3] = __expf(sc[jj][3] - mn1);
                s0 += sc[jj][0] + sc[jj][1];
                s1 += sc[jj][2] + sc[jj][3];
            }
            s0 += __shfl_xor_sync(0xffffffffu, s0, 1);
            s0 += __shfl_xor_sync(0xffffffffu, s0, 2);
            s1 += __shfl_xor_sync(0xffffffffu, s1, 1);
            s1 += __shfl_xor_sync(0xffffffffu, s1, 2);
            l0 = l0 * a0 + s0; l1 = l1 * a1 + s1;
            m0 = mn0; m1 = mn1;
            #pragma unroll
            for (int jj = 0; jj < 8; jj++) {
                o[jj][0] *= a0; o[jj][1] *= a0;
                o[jj][2] *= a1; o[jj][3] *= a1;
            }

            // ---- P -> smem (RN-rounded to tf32: unbiased PV mma) ----
            #pragma unroll
            for (int jj = 0; jj < 8; jj++) {
                *(float2*)&Ps[g * VSTR + jj * 8 + 2 * c] =
                    make_float2(to_tf32(sc[jj][0]), to_tf32(sc[jj][1]));
                *(float2*)&Ps[(g + 8) * VSTR + jj * 8 + 2 * c] =
                    make_float2(to_tf32(sc[jj][2]), to_tf32(sc[jj][3]));
            }
            __syncwarp();

            // ---- O += P @ V ----
            #pragma unroll
            for (int kk = 0; kk < 8; kk++) {
                uint32_t af[4];
                af[0] = __float_as_uint(Ps[g * VSTR + kk * 8 + c]);
                af[1] = __float_as_uint(Ps[(g + 8) * VSTR + kk * 8 + c]);
                af[2] = __float_as_uint(Ps[g * VSTR + kk * 8 + c + 4]);
                af[3] = __float_as_uint(Ps[(g + 8) * VSTR + kk * 8 + c + 4]);
                uint32_t bf[8][2];
                #pragma unroll
                for (int jj = 0; jj < 8; jj++) {
                    bf[jj][0] = __float_as_uint(Vs[(kk * 8 + c) * VSTR + jj * 8 + g]);
                    bf[jj][1] = __float_as_uint(Vs[(kk * 8 + c + 4) * VSTR + jj * 8 + g]);
                }
                #pragma unroll
                for (int jj = 0; jj < 8; jj++)
                    mma_tf32(o[jj], af, bf[jj]);
            }
            __syncwarp();
        }
        __syncthreads();
    }

    // ---- epilogue: normalize, RN-round (feeds Wo tf32 GEMM), store ----
    const float il0 = 1.f / l0, il1 = 1.f / l1;
    #pragma unroll
    for (int jj = 0; jj < 8; jj++) {
        const int col = jj * 8 + 2 * c;
        *(float2*)&AH[rb + (size_t)qrow0 * E_ + col] =
            make_float2(to_tf32(o[jj][0] * il0), to_tf32(o[jj][1] * il0));
        *(float2*)&AH[rb + (size_t)(qrow0 + 8) * E_ + col] =
            make_float2(to_tf32(o[jj][2] * il1), to_tf32(o[jj][3] * il1));
    }
}

// ===========================================================================
extern "C" void kernel_launch(void* const* d_in, const int* in_sizes, int n_in,
                              void* d_out, int out_size)
{
    const float* q  = (const float*)d_in[0];
    const float* k  = (const float*)d_in[1];
    const float* v  = (const float*)d_in[2];
    const float* Wq = (const float*)d_in[3];
    const float* Wk = (const float*)d_in[4];
    const float* Wv = (const float*)d_in[5];
    const float* bv = (const float*)d_in[6];
    const float* Wo = (const float*)d_in[7];
    const float* bo = (const float*)d_in[8];
    float* out = (float*)d_out;

    float *qh, *kh, *vh, *ah, *qr, *kr, *vr, *wr;
    cudaGetSymbolAddress((void**)&qh, g_qh);
    cudaGetSymbolAddress((void**)&kh, g_kh);
    cudaGetSymbolAddress((void**)&vh, g_vh);
    cudaGetSymbolAddress((void**)&ah, g_ah);
    cudaGetSymbolAddress((void**)&qr, g_qr);
    cudaGetSymbolAddress((void**)&kr, g_kr);
    cudaGetSymbolAddress((void**)&vr, g_vr);
    cudaGetSymbolAddress((void**)&wr, g_wr);

    cudaFuncSetAttribute(gemm_mma, cudaFuncAttributeMaxDynamicSharedMemorySize,
                         GEMM_SMEM);
    cudaFuncSetAttribute(attn_mma, cudaFuncAttributeMaxDynamicSharedMemorySize,
                         ATTN_SMEM);

    // ---- tf32 prepass ----
    const int n4_act = (M_ * E_) / 4;
    const int n4_w   = (E_ * E_) / 4;
    round_tf32_kernel<<<(n4_act + 255) / 256, 256>>>(q, qr, n4_act);
    round_tf32_kernel<<<(n4_act + 255) / 256, 256>>>(k, kr, n4_act);
    round_tf32_kernel<<<(n4_act + 255) / 256, 256>>>(v, vr, n4_act);
    round_tf32_kernel<<<(n4_w + 255) / 256, 256>>>(Wq, wr + 0 * E_ * E_, n4_w);
    round_tf32_kernel<<<(n4_w + 255) / 256, 256>>>(Wk, wr + 1 * E_ * E_, n4_w);
    round_tf32_kernel<<<(n4_w + 255) / 256, 256>>>(Wv, wr + 2 * E_ * E_, n4_w);
    round_tf32_kernel<<<(n4_w + 255) / 256, 256>>>(Wo, wr + 3 * E_ * E_, n4_w);

    // ---- projections (outputs RN-rounded to tf32 for the attention mmas) ----
    const dim3 ggrd1(M_ / GTM, E_ / GTN, 1);
    const dim3 ggrd2(M_ / GTM, E_ / GTN, 2);
    gemm_mma<<<ggrd2, 256, GEMM_SMEM>>>(qr, kr, wr, wr + E_ * E_, qh, kh, nullptr, 1);
    gemm_mma<<<ggrd1, 256, GEMM_SMEM>>>(vr, vr, wr + 2 * E_ * E_, nullptr, vh, nullptr, bv, 1);

    // ---- attention (tensor cores) ----
    const dim3 agrd(S_ / AQ, B_ * H_);    // (16, 32)
    attn_mma<<<agrd, 256, ATTN_SMEM>>>(qh, kh, vh, ah);

    // ---- output projection (full fp32 out) ----
    gemm_mma<<<ggrd1, 256, GEMM_SMEM>>>(ah, ah, wr + 3 * E_ * E_, nullptr, out, nullptr, bo, 0);
}

// round 5
// speedup vs baseline: 4.1018x; 1.0221x over previous
#include <cuda_runtime.h>
#include <cstdint>

// Problem constants
#define B_   2
#define S_   2048
#define E_   1024
#define H_   16
#define HD_  64
#define M_   (B_ * S_)   // 4096 flattened rows

// Scratch
__device__ float g_qh[M_ * E_];
__device__ float g_kh[M_ * E_];
__device__ float g_vh[M_ * E_];
__device__ float g_ah[M_ * E_];

// ===========================================================================
// Helpers
// ===========================================================================
__device__ __forceinline__ uint32_t smem_u32(const void* p) {
    uint32_t a;
    asm("{ .reg .u64 t; cvta.to.shared.u64 t, %1; cvt.u32.u64 %0, t; }"
        : "=r"(a) : "l"(p));
    return a;
}

__device__ __forceinline__ float to_tf32(float x) {
    uint32_t u;
    asm("cvt.rna.tf32.f32 %0, %1;" : "=r"(u) : "f"(x));
    return __uint_as_float(u);
}

__device__ __forceinline__ uint32_t tf32_bits(float x) {
    uint32_t u;
    asm("cvt.rna.tf32.f32 %0, %1;" : "=r"(u) : "f"(x));
    return u;
}

__device__ __forceinline__ void cp_async16(uint32_t dst, const void* src) {
    asm volatile("cp.async.cg.shared.global [%0], [%1], 16;"
                 :: "r"(dst), "l"(src) : "memory");
}
#define CP_COMMIT() asm volatile("cp.async.commit_group;" ::: "memory")
#define CP_WAIT1()  asm volatile("cp.async.wait_group 1;" ::: "memory")

__device__ __forceinline__ void mma_tf32(float* d, const uint32_t* a, const uint32_t* b) {
    asm volatile(
        "mma.sync.aligned.m16n8k8.row.col.f32.tf32.tf32.f32 "
        "{%0,%1,%2,%3}, {%4,%5,%6,%7}, {%8,%9}, {%0,%1,%2,%3};"
        : "+f"(d[0]), "+f"(d[1]), "+f"(d[2]), "+f"(d[3])
        : "r"(a[0]), "r"(a[1]), "r"(a[2]), "r"(a[3]), "r"(b[0]), "r"(b[1]));
}

// ===========================================================================
// mma.sync tf32 GEMM:  C[M,1024] = A[M,1024] @ W[1024,1024]^T (+ bias)
// Fragments RN-rounded to tf32 at smem->reg gather (no prepass needed).
// blockIdx.z selects one of up to 3 (A, W, C, bias) problems.
// round_out: RN-round result to tf32 (for GEMMs feeding later tf32 mmas).
// ===========================================================================
#define GTM   128
#define GTN   256
#define GTK   32
#define NCH   (E_ / GTK)
#define LDS_  36
#define STG_FLOATS ((GTM + GTN) * LDS_)
#define STG_BYTES  (STG_FLOATS * 4)
#define NSTG  3
#define GEMM_SMEM (NSTG * STG_BYTES)

__global__ __launch_bounds__(256, 1) void gemm_mma(
    const float* __restrict__ A0, const float* __restrict__ A1,
    const float* __restrict__ A2,
    const float* __restrict__ W0, const float* __restrict__ W1,
    const float* __restrict__ W2,
    float* __restrict__ C0, float* __restrict__ C1, float* __restrict__ C2,
    const float* __restrict__ b0, const float* __restrict__ b1,
    const float* __restrict__ b2, int round_out)
{
    extern __shared__ float smem[];
    const int tid  = threadIdx.x;
    const int lane = tid & 31;
    const int wid  = tid >> 5;
    const int wm   = wid >> 2;
    const int wn   = wid & 3;

    const int z = blockIdx.z;
    const float* A = (z == 0) ? A0 : (z == 1) ? A1 : A2;
    const float* W = (z == 0) ? W0 : (z == 1) ? W1 : W2;
    float*       C = (z == 0) ? C0 : (z == 1) ? C1 : C2;
    const float* bias = (z == 0) ? b0 : (z == 1) ? b1 : b2;

    const int m0 = blockIdx.x * GTM;
    const int n0 = blockIdx.y * GTN;
    const uint32_t sb = smem_u32(smem);

    float acc[4][8][4] = {};

    auto load_chunk = [&](int ch, int stg) {
        const int k0 = ch * GTK;
        const uint32_t as = sb + stg * STG_BYTES;
        const uint32_t bs = as + GTM * LDS_ * 4;
        #pragma unroll
        for (int it = 0; it < 4; it++) {
            const int idx = tid + it * 256;
            const int r = idx >> 3, c4 = idx & 7;
            cp_async16(as + r * (LDS_ * 4) + c4 * 16,
                       A + (size_t)(m0 + r) * E_ + k0 + c4 * 4);
        }
        #pragma unroll
        for (int it = 0; it < 8; it++) {
            const int idx = tid + it * 256;
            const int r = idx >> 3, c4 = idx & 7;
            cp_async16(bs + r * (LDS_ * 4) + c4 * 16,
                       W + (size_t)(n0 + r) * E_ + k0 + c4 * 4);
        }
    };

    load_chunk(0, 0); CP_COMMIT();
    load_chunk(1, 1); CP_COMMIT();

    const int g = lane >> 2;
    const int c = lane & 3;

    for (int i = 0; i < NCH; i++) {
        CP_WAIT1();
        __syncthreads();
        if (i + 2 < NCH) load_chunk(i + 2, (i + 2) % NSTG);
        CP_COMMIT();

        const float* as = smem + (i % NSTG) * STG_FLOATS;
        const float* bs = as + GTM * LDS_;

        #pragma unroll
        for (int kk = 0; kk < 4; kk++) {
            const int k8 = kk * 8;
            uint32_t af[4][4], bf[8][2];
            #pragma unroll
            for (int ii = 0; ii < 4; ii++) {
                const int r = wm * 64 + ii * 16 + g;
                af[ii][0] = tf32_bits(as[r * LDS_ + k8 + c]);
                af[ii][1] = tf32_bits(as[(r + 8) * LDS_ + k8 + c]);
                af[ii][2] = tf32_bits(as[r * LDS_ + k8 + c + 4]);
                af[ii][3] = tf32_bits(as[(r + 8) * LDS_ + k8 + c + 4]);
            }
            #pragma unroll
            for (int jj = 0; jj < 8; jj++) {
                const int n = wn * 64 + jj * 8 + g;
                bf[jj][0] = tf32_bits(bs[n * LDS_ + k8 + c]);
                bf[jj][1] = tf32_bits(bs[n * LDS_ + k8 + c + 4]);
            }
            #pragma unroll
            for (int ii = 0; ii < 4; ii++)
                #pragma unroll
                for (int jj = 0; jj < 8; jj++)
                    mma_tf32(acc[ii][jj], af[ii], bf[jj]);
        }
    }

    #pragma unroll
    for (int ii = 0; ii < 4; ii++) {
        const int r0 = m0 + wm * 64 + ii * 16 + g;
        #pragma unroll
        for (int jj = 0; jj < 8; jj++) {
            const int cc = n0 + wn * 64 + jj * 8 + 2 * c;
            float bx = 0.f, by = 0.f;
            if (bias) { bx = bias[cc]; by = bias[cc + 1]; }
            float2 v0 = make_float2(acc[ii][jj][0] + bx, acc[ii][jj][1] + by);
            float2 v1 = make_float2(acc[ii][jj][2] + bx, acc[ii][jj][3] + by);
            if (round_out) {
                v0.x = to_tf32(v0.x); v0.y = to_tf32(v0.y);
                v1.x = to_tf32(v1.x); v1.y = to_tf32(v1.y);
            }
            *(float2*)&C[(size_t)r0 * E_ + cc]       = v0;
            *(float2*)&C[(size_t)(r0 + 8) * E_ + cc] = v1;
        }
    }
}

// ===========================================================================
// Tensor-core flash attention (tf32 mma), strict-causal with (0,0) exception.
// CTA = (b,h) x 128 q-rows; 8 warps x 16 rows; K/V blocks of 64, cp.async x2.
// Inputs qh/kh/vh are already RN-rounded tf32 values (GEMM round_out=1).
// ===========================================================================
#define AQ    128
#define AK    64
#define QSTR  68
#define VSTR  72
#define KS_FLOATS (AK * QSTR)
#define VS_FLOATS (AK * VSTR)
#define QP_FLOATS (8 * 16 * VSTR)
#define OFF_K  QP_FLOATS
#define OFF_V  (OFF_K + 2 * KS_FLOATS)
#define ATTN_SMEM ((OFF_V + 2 * VS_FLOATS) * 4)

__global__ __launch_bounds__(256, 1) void attn_mma(
    const float* __restrict__ QH, const float* __restrict__ KH,
    const float* __restrict__ VH, float* __restrict__ AH)
{
    extern __shared__ float sm[];
    const int tid  = threadIdx.x;
    const int lane = tid & 31;
    const int w    = tid >> 5;
    const int g    = lane >> 2;
    const int c    = lane & 3;
    const int qi   = (int)(gridDim.x - 1) - (int)blockIdx.x;  // heavy tiles first
    const int bh   = blockIdx.y;
    const int b    = bh >> 4;
    const int h    = bh & 15;
    const int qbase = qi * AQ;
    const size_t rb = (size_t)b * S_ * E_ + (size_t)h * HD_;

    float* Qs = sm;
    float* Ps = sm + w * (16 * VSTR);
    const uint32_t sb = smem_u32(sm);

    #pragma unroll
    for (int it = 0; it < 8; it++) {
        const int idx = tid + it * 256;
        const int r = idx >> 4, c4 = idx & 15;
        float4 v = *(const float4*)&QH[rb + (size_t)(qbase + r) * E_ + c4 * 4];
        *(float4*)&Qs[r * QSTR + c4 * 4] = v;
    }
    __syncthreads();
    uint32_t qf[8][4];
    {
        const float* qw = Qs + (w * 16) * QSTR;
        #pragma unroll
        for (int kk = 0; kk < 8; kk++) {
            qf[kk][0] = __float_as_uint(qw[g * QSTR + kk * 8 + c]);
            qf[kk][1] = __float_as_uint(qw[(g + 8) * QSTR + kk * 8 + c]);
            qf[kk][2] = __float_as_uint(qw[g * QSTR + kk * 8 + c + 4]);
            qf[kk][3] = __float_as_uint(qw[(g + 8) * QSTR + kk * 8 + c + 4]);
        }
    }
    __syncthreads();

    float o[8][4] = {};
    float m0 = -1e30f, m1 = -1e30f, l0 = 0.f, l1 = 0.f;
    const int nb = 2 * qi + 2;
    const int qrow0 = qbase + w * 16 + g;
    const int wmin  = qbase + w * 16;
    const int wmax  = wmin + 15;

    auto loadKV = [&](int kb, int stg) {
        const int t0 = kb * AK;
        const uint32_t ks = sb + (OFF_K + stg * KS_FLOATS) * 4;
        const uint32_t vs = sb + (OFF_V + stg * VS_FLOATS) * 4;
        #pragma unroll
        for (int it = 0; it < 4; it++) {
            const int idx = tid + it * 256;
            const int r = idx >> 4, c4 = idx & 15;
            cp_async16(ks + (r * QSTR + c4 * 4) * 4,
                       &KH[rb + (size_t)(t0 + r) * E_ + c4 * 4]);
            cp_async16(vs + (r * VSTR + c4 * 4) * 4,
                       &VH[rb + (size_t)(t0 + r) * E_ + c4 * 4]);
        }
    };

    loadKV(0, 0); CP_COMMIT();

    for (int kb = 0; kb < nb; kb++) {
        const int stg = kb & 1;
        const int t0  = kb * AK;
        if (kb + 1 < nb) loadKV(kb + 1, stg ^ 1);
        CP_COMMIT();
        CP_WAIT1();
        __syncthreads();

        if (t0 <= wmax) {
            const float* Ks = sm + OFF_K + stg * KS_FLOATS;
            const float* Vs = sm + OFF_V + stg * VS_FLOATS;

            float sc[8][4] = {};
            #pragma unroll
            for (int kk = 0; kk < 8; kk++) {
                uint32_t bf[8][2];
                #pragma unroll
                for (int jj = 0; jj < 8; jj++) {
                    const int n = jj * 8 + g;
                    bf[jj][0] = __float_as_uint(Ks[n * QSTR + kk * 8 + c]);
                    bf[jj][1] = __float_as_uint(Ks[n * QSTR + kk * 8 + c + 4]);
                }
                #pragma unroll
                for (int jj = 0; jj < 8; jj++)
                    mma_tf32(sc[jj], qf[kk], bf[jj]);
            }

            const bool needmask = (t0 + AK - 1) >= wmin;
            #pragma unroll
            for (int jj = 0; jj < 8; jj++) {
                sc[jj][0] *= 0.125f; sc[jj][1] *= 0.125f;
                sc[jj][2] *= 0.125f; sc[jj][3] *= 0.125f;
                if (needmask) {
                    const int cg = t0 + jj * 8 + 2 * c;
                    const int r0 = qrow0, r1 = qrow0 + 8;
                    if (!((cg     < r0) || (r0 == 0 && cg == 0)))     sc[jj][0] = -1e30f;
                    if (!((cg + 1 < r0) || (r0 == 0 && cg + 1 == 0))) sc[jj][1] = -1e30f;
                    if (!(cg     < r1)) sc[jj][2] = -1e30f;
                    if (!(cg + 1 < r1)) sc[jj][3] = -1e30f;
                }
            }

            float mx0 = -1e30f, mx1 = -1e30f;
            #pragma unroll
            for (int jj = 0; jj < 8; jj++) {
                mx0 = fmaxf(mx0, fmaxf(sc[jj][0], sc[jj][1]));
                mx1 = fmaxf(mx1, fmaxf(sc[jj][2], sc[jj][3]));
            }
            mx0 = fmaxf(mx0, __shfl_xor_sync(0xffffffffu, mx0, 1));
            mx0 = fmaxf(mx0, __shfl_xor_sync(0xffffffffu, mx0, 2));
            mx1 = fmaxf(mx1, __shfl_xor_sync(0xffffffffu, mx1, 1));
            mx1 = fmaxf(mx1, __shfl_xor_sync(0xffffffffu, mx1, 2));
            const float mn0 = fmaxf(m0, mx0), mn1 = fmaxf(m1, mx1);
            const float a0 = __expf(m0 - mn0), a1 = __expf(m1 - mn1);
            float s0 = 0.f, s1 = 0.f;
            #pragma unroll
            for (int jj = 0; jj < 8; jj++) {
                sc[jj][0] = __expf(sc[jj][0] - mn0);
                sc[jj][1] = __expf(sc[jj][1] - mn0);
                sc[jj][2] = __expf(sc[jj][2] - mn1);
                sc[jj][3] = __expf(sc[jj][3] - mn1);
                s0 += sc[jj][0] + sc[jj][1];
                s1 += sc[jj][2] + sc[jj][3];
            }
            s0 += __shfl_xor_sync(0xffffffffu, s0, 1);
            s0 += __shfl_xor_sync(0xffffffffu, s0, 2);
            s1 += __shfl_xor_sync(0xffffffffu, s1, 1);
            s1 += __shfl_xor_sync(0xffffffffu, s1, 2);
            l0 = l0 * a0 + s0; l1 = l1 * a1 + s1;
            m0 = mn0; m1 = mn1;
            #pragma unroll
            for (int jj = 0; jj < 8; jj++) {
                o[jj][0] *= a0; o[jj][1] *= a0;
                o[jj][2] *= a1; o[jj][3] *= a1;
            }

            #pragma unroll
            for (int jj = 0; jj < 8; jj++) {
                *(float2*)&Ps[g * VSTR + jj * 8 + 2 * c] =
                    make_float2(to_tf32(sc[jj][0]), to_tf32(sc[jj][1]));
                *(float2*)&Ps[(g + 8) * VSTR + jj * 8 + 2 * c] =
                    make_float2(to_tf32(sc[jj][2]), to_tf32(sc[jj][3]));
            }
            __syncwarp();

            #pragma unroll
            for (int kk = 0; kk < 8; kk++) {
                uint32_t af[4];
                af[0] = __float_as_uint(Ps[g * VSTR + kk * 8 + c]);
                af[1] = __float_as_uint(Ps[(g + 8) * VSTR + kk * 8 + c]);
                af[2] = __float_as_uint(Ps[g * VSTR + kk * 8 + c + 4]);
                af[3] = __float_as_uint(Ps[(g + 8) * VSTR + kk * 8 + c + 4]);
                uint32_t bf[8][2];
                #pragma unroll
                for (int jj = 0; jj < 8; jj++) {
                    bf[jj][0] = __float_as_uint(Vs[(kk * 8 + c) * VSTR + jj * 8 + g]);
                    bf[jj][1] = __float_as_uint(Vs[(kk * 8 + c + 4) * VSTR + jj * 8 + g]);
                }
                #pragma unroll
                for (int jj = 0; jj < 8; jj++)
                    mma_tf32(o[jj], af, bf[jj]);
            }
            __syncwarp();
        }
        __syncthreads();
    }

    const float il0 = 1.f / l0, il1 = 1.f / l1;
    #pragma unroll
    for (int jj = 0; jj < 8; jj++) {
        const int col = jj * 8 + 2 * c;
        *(float2*)&AH[rb + (size_t)qrow0 * E_ + col] =
            make_float2(o[jj][0] * il0, o[jj][1] * il0);
        *(float2*)&AH[rb + (size_t)(qrow0 + 8) * E_ + col] =
            make_float2(o[jj][2] * il1, o[jj][3] * il1);
    }
}

// ===========================================================================
extern "C" void kernel_launch(void* const* d_in, const int* in_sizes, int n_in,
                              void* d_out, int out_size)
{
    const float* q  = (const float*)d_in[0];
    const float* k  = (const float*)d_in[1];
    const float* v  = (const float*)d_in[2];
    const float* Wq = (const float*)d_in[3];
    const float* Wk = (const float*)d_in[4];
    const float* Wv = (const float*)d_in[5];
    const float* bv = (const float*)d_in[6];
    const float* Wo = (const float*)d_in[7];
    const float* bo = (const float*)d_in[8];
    float* out = (float*)d_out;

    float *qh, *kh, *vh, *ah;
    cudaGetSymbolAddress((void**)&qh, g_qh);
    cudaGetSymbolAddress((void**)&kh, g_kh);
    cudaGetSymbolAddress((void**)&vh, g_vh);
    cudaGetSymbolAddress((void**)&ah, g_ah);

    cudaFuncSetAttribute(gemm_mma, cudaFuncAttributeMaxDynamicSharedMemorySize,
                         GEMM_SMEM);
    cudaFuncSetAttribute(attn_mma, cudaFuncAttributeMaxDynamicSharedMemorySize,
                         ATTN_SMEM);

    // ---- fused Q/K/V projections (one launch, z selects problem) ----
    const dim3 ggrd3(M_ / GTM, E_ / GTN, 3);
    gemm_mma<<<ggrd3, 256, GEMM_SMEM>>>(q, k, v, Wq, Wk, Wv, qh, kh, vh,
                                        nullptr, nullptr, bv, 1);

    // ---- attention (tensor cores) ----
    const dim3 agrd(S_ / AQ, B_ * H_);
    attn_mma<<<agrd, 256, ATTN_SMEM>>>(qh, kh, vh, ah);

    // ---- output projection (full fp32 out) ----
    const dim3 ggrd1(M_ / GTM, E_ / GTN, 1);
    gemm_mma<<<ggrd1, 256, GEMM_SMEM>>>(ah, ah, ah, Wo, Wo, Wo, out, out, out,
                                        bo, bo, bo, 0);
}

// round 6
// speedup vs baseline: 4.1719x; 1.0171x over previous
#include <cuda_runtime.h>
#include <cstdint>

// Problem constants
#define B_   2
#define S_   2048
#define E_   1024
#define H_   16
#define HD_  64
#define M_   (B_ * S_)   // 4096 flattened rows

// Scratch
__device__ float g_qh[M_ * E_];
__device__ float g_kh[M_ * E_];
__device__ float g_vh[M_ * E_];
__device__ float g_ah[M_ * E_];
__device__ float g_qr[M_ * E_];       // tf32-rounded q,k,v
__device__ float g_kr[M_ * E_];
__device__ float g_vr[M_ * E_];
__device__ float g_wr[4 * E_ * E_];   // tf32-rounded Wq,Wk,Wv,Wo

// ===========================================================================
// Helpers
// ===========================================================================
__device__ __forceinline__ uint32_t smem_u32(const void* p) {
    uint32_t a;
    asm("{ .reg .u64 t; cvta.to.shared.u64 t, %1; cvt.u32.u64 %0, t; }"
        : "=r"(a) : "l"(p));
    return a;
}

__device__ __forceinline__ float to_tf32(float x) {
    uint32_t u;
    asm("cvt.rna.tf32.f32 %0, %1;" : "=r"(u) : "f"(x));
    return __uint_as_float(u);
}

__device__ __forceinline__ void cp_async16(uint32_t dst, const void* src) {
    asm volatile("cp.async.cg.shared.global [%0], [%1], 16;"
                 :: "r"(dst), "l"(src) : "memory");
}
#define CP_COMMIT() asm volatile("cp.async.commit_group;" ::: "memory")
#define CP_WAIT1()  asm volatile("cp.async.wait_group 1;" ::: "memory")

__device__ __forceinline__ void mma_tf32(float* d, const uint32_t* a, const uint32_t* b) {
    asm volatile(
        "mma.sync.aligned.m16n8k8.row.col.f32.tf32.tf32.f32 "
        "{%0,%1,%2,%3}, {%4,%5,%6,%7}, {%8,%9}, {%0,%1,%2,%3};"
        : "+f"(d[0]), "+f"(d[1]), "+f"(d[2]), "+f"(d[3])
        : "r"(a[0]), "r"(a[1]), "r"(a[2]), "r"(a[3]), "r"(b[0]), "r"(b[1]));
}

__device__ __forceinline__ void ldsm4(uint32_t* r, uint32_t addr) {
    asm volatile("ldmatrix.sync.aligned.m8n8.x4.shared.b16 {%0,%1,%2,%3}, [%4];"
                 : "=r"(r[0]), "=r"(r[1]), "=r"(r[2]), "=r"(r[3]) : "r"(addr));
}

// ===========================================================================
// Fused tf32 rounding prepass: q,k,v,Wq,Wk,Wv,Wo -> qr,kr,vr,wr (one launch)
// ===========================================================================
#define ACT4 (M_ * E_ / 4)   // 1048576 float4 per activation
#define W4   (E_ * E_ / 4)   // 262144 float4 per weight
#define TOT4 (3 * ACT4 + 4 * W4)

__global__ __launch_bounds__(256) void round_all(
    const float4* __restrict__ q, const float4* __restrict__ k,
    const float4* __restrict__ v,
    const float4* __restrict__ Wq, const float4* __restrict__ Wk,
    const float4* __restrict__ Wv, const float4* __restrict__ Wo,
    float4* __restrict__ qr, float4* __restrict__ kr,
    float4* __restrict__ vr, float4* __restrict__ wr)
{
    const long i = (long)blockIdx.x * 256 + threadIdx.x;
    if (i >= TOT4) return;
    const float4* s; float4* d; long off;
    if (i < ACT4)               { s = q;  d = qr; off = i; }
    else if (i < 2L * ACT4)     { s = k;  d = kr; off = i - ACT4; }
    else if (i < 3L * ACT4)     { s = v;  d = vr; off = i - 2L * ACT4; }
    else {
        const long j = i - 3L * ACT4;
        s = (j < W4) ? Wq : (j < 2 * W4) ? Wk : (j < 3 * W4) ? Wv : Wo;
        d = wr + (j / W4) * W4;
        off = j % W4;
    }
    float4 x = s[off];
    x.x = to_tf32(x.x); x.y = to_tf32(x.y);
    x.z = to_tf32(x.z); x.w = to_tf32(x.w);
    d[off] = x;
}

// ===========================================================================
// mma.sync tf32 GEMM:  C[M,1024] = A[M,1024] @ W[1024,1024]^T (+ bias)
// Inputs MUST already be tf32-rounded. ldmatrix.x4 fragment loads.
// blockIdx.z selects one of up to 3 (A, W, C, bias) problems.
// ===========================================================================
#define GTM   128
#define GTN   256
#define GTK   32
#define NCH   (E_ / GTK)
#define LDS_  36
#define STG_FLOATS ((GTM + GTN) * LDS_)
#define STG_BYTES  (STG_FLOATS * 4)
#define NSTG  3
#define GEMM_SMEM (NSTG * STG_BYTES)

__global__ __launch_bounds__(256, 1) void gemm_mma(
    const float* __restrict__ A0, const float* __restrict__ A1,
    const float* __restrict__ A2,
    const float* __restrict__ W0, const float* __restrict__ W1,
    const float* __restrict__ W2,
    float* __restrict__ C0, float* __restrict__ C1, float* __restrict__ C2,
    const float* __restrict__ b0, const float* __restrict__ b1,
    const float* __restrict__ b2, int round_out)
{
    extern __shared__ float smem[];
    const int tid  = threadIdx.x;
    const int lane = tid & 31;
    const int wid  = tid >> 5;
    const int wm   = wid >> 2;
    const int wn   = wid & 3;

    const int z = blockIdx.z;
    const float* A = (z == 0) ? A0 : (z == 1) ? A1 : A2;
    const float* W = (z == 0) ? W0 : (z == 1) ? W1 : W2;
    float*       C = (z == 0) ? C0 : (z == 1) ? C1 : C2;
    const float* bias = (z == 0) ? b0 : (z == 1) ? b1 : b2;

    const int m0 = blockIdx.x * GTM;
    const int n0 = blockIdx.y * GTN;
    const uint32_t sb = smem_u32(smem);

    // ldmatrix per-lane byte offsets (within a stage)
    // A matrices (per ii): rows 0-15 of 16-row tile; lanes 0-15 -> col k8,
    // lanes 16-31 -> col k8+4 (x4 = {r0-7,k0-3},{r8-15,k0-3},{r0-7,k4-7},{r8-15,k4-7})
    uint32_t aoff[4], boff[4];
    #pragma unroll
    for (int ii = 0; ii < 4; ii++)
        aoff[ii] = ((wm * 64 + ii * 16 + (lane & 15)) * LDS_ + ((lane >> 4) << 2)) * 4;
    // B matrices (per jj-pair jp): x4 = {n0-7,k0-3},{n0-7,k4-7},{n8-15,k0-3},{n8-15,k4-7}
    #pragma unroll
    for (int jp = 0; jp < 4; jp++)
        boff[jp] = (GTM * LDS_
                    + (wn * 64 + jp * 16 + ((lane >> 4) << 3) + (lane & 7)) * LDS_
                    + ((lane >> 3) & 1) * 4) * 4;

    float acc[4][8][4] = {};

    auto load_chunk = [&](int ch, int stg) {
        const int k0 = ch * GTK;
        const uint32_t as = sb + stg * STG_BYTES;
        const uint32_t bs = as + GTM * LDS_ * 4;
        #pragma unroll
        for (int it = 0; it < 4; it++) {
            const int idx = tid + it * 256;
            const int r = idx >> 3, c4 = idx & 7;
            cp_async16(as + r * (LDS_ * 4) + c4 * 16,
                       A + (size_t)(m0 + r) * E_ + k0 + c4 * 4);
        }
        #pragma unroll
        for (int it = 0; it < 8; it++) {
            const int idx = tid + it * 256;
            const int r = idx >> 3, c4 = idx & 7;
            cp_async16(bs + r * (LDS_ * 4) + c4 * 16,
                       W + (size_t)(n0 + r) * E_ + k0 + c4 * 4);
        }
    };

    load_chunk(0, 0); CP_COMMIT();
    load_chunk(1, 1); CP_COMMIT();

    for (int i = 0; i < NCH; i++) {
        CP_WAIT1();
        __syncthreads();
        if (i + 2 < NCH) load_chunk(i + 2, (i + 2) % NSTG);
        CP_COMMIT();

        const uint32_t su = sb + (i % NSTG) * STG_BYTES;

        #pragma unroll
        for (int kk = 0; kk < 4; kk++) {
            const uint32_t kb = su + kk * 32;  // k8 step = 8 floats = 32 bytes
            uint32_t af[4][4], bf[4][4];
            #pragma unroll
            for (int ii = 0; ii < 4; ii++) ldsm4(af[ii], kb + aoff[ii]);
            #pragma unroll
            for (int jp = 0; jp < 4; jp++) ldsm4(bf[jp], kb + boff[jp]);
            // bf[jp] = { b(2jp)[0], b(2jp)[1], b(2jp+1)[0], b(2jp+1)[1] }
            #pragma unroll
            for (int ii = 0; ii < 4; ii++)
                #pragma unroll
                for (int jp = 0; jp < 4; jp++) {
                    mma_tf32(acc[ii][2 * jp],     af[ii], &bf[jp][0]);
                    mma_tf32(acc[ii][2 * jp + 1], af[ii], &bf[jp][2]);
                }
        }
    }

    const int g = lane >> 2;
    const int c = lane & 3;
    #pragma unroll
    for (int ii = 0; ii < 4; ii++) {
        const int r0 = m0 + wm * 64 + ii * 16 + g;
        #pragma unroll
        for (int jj = 0; jj < 8; jj++) {
            const int cc = n0 + wn * 64 + jj * 8 + 2 * c;
            float bx = 0.f, by = 0.f;
            if (bias) { bx = bias[cc]; by = bias[cc + 1]; }
            float2 v0 = make_float2(acc[ii][jj][0] + bx, acc[ii][jj][1] + by);
            float2 v1 = make_float2(acc[ii][jj][2] + bx, acc[ii][jj][3] + by);
            if (round_out) {
                v0.x = to_tf32(v0.x); v0.y = to_tf32(v0.y);
                v1.x = to_tf32(v1.x); v1.y = to_tf32(v1.y);
            }
            *(float2*)&C[(size_t)r0 * E_ + cc]       = v0;
            *(float2*)&C[(size_t)(r0 + 8) * E_ + cc] = v1;
        }
    }
}

// ===========================================================================
// Tensor-core flash attention (tf32 mma), strict-causal with (0,0) exception.
// CTA = (b,h) x 128 q-rows; 8 warps x 16 rows; K/V blocks of 64, cp.async x2.
// Inputs qh/kh/vh already RN-rounded tf32; output ah RN-rounded for Wo GEMM.
// ===========================================================================
#define AQ    128
#define AK    64
#define QSTR  68
#define VSTR  72
#define KS_FLOATS (AK * QSTR)
#define VS_FLOATS (AK * VSTR)
#define QP_FLOATS (8 * 16 * VSTR)
#define OFF_K  QP_FLOATS
#define OFF_V  (OFF_K + 2 * KS_FLOATS)
#define ATTN_SMEM ((OFF_V + 2 * VS_FLOATS) * 4)

__global__ __launch_bounds__(256, 1) void attn_mma(
    const float* __restrict__ QH, const float* __restrict__ KH,
    const float* __restrict__ VH, float* __restrict__ AH)
{
    extern __shared__ float sm[];
    const int tid  = threadIdx.x;
    const int lane = tid & 31;
    const int w    = tid >> 5;
    const int g    = lane >> 2;
    const int c    = lane & 3;
    const int qi   = (int)(gridDim.x - 1) - (int)blockIdx.x;  // heavy tiles first
    const int bh   = blockIdx.y;
    const int b    = bh >> 4;
    const int h    = bh & 15;
    const int qbase = qi * AQ;
    const size_t rb = (size_t)b * S_ * E_ + (size_t)h * HD_;

    float* Qs = sm;
    float* Ps = sm + w * (16 * VSTR);
    const uint32_t sb = smem_u32(sm);

    #pragma unroll
    for (int it = 0; it < 8; it++) {
        const int idx = tid + it * 256;
        const int r = idx >> 4, c4 = idx & 15;
        float4 v = *(const float4*)&QH[rb + (size_t)(qbase + r) * E_ + c4 * 4];
        *(float4*)&Qs[r * QSTR + c4 * 4] = v;
    }
    __syncthreads();
    uint32_t qf[8][4];
    {
        const float* qw = Qs + (w * 16) * QSTR;
        #pragma unroll
        for (int kk = 0; kk < 8; kk++) {
            qf[kk][0] = __float_as_uint(qw[g * QSTR + kk * 8 + c]);
            qf[kk][1] = __float_as_uint(qw[(g + 8) * QSTR + kk * 8 + c]);
            qf[kk][2] = __float_as_uint(qw[g * QSTR + kk * 8 + c + 4]);
            qf[kk][3] = __float_as_uint(qw[(g + 8) * QSTR + kk * 8 + c + 4]);
        }
    }
    __syncthreads();

    float o[8][4] = {};
    float m0 = -1e30f, m1 = -1e30f, l0 = 0.f, l1 = 0.f;
    const int nb = 2 * qi + 2;
    const int qrow0 = qbase + w * 16 + g;
    const int wmin  = qbase + w * 16;
    const int wmax  = wmin + 15;

    auto loadKV = [&](int kb, int stg) {
        const int t0 = kb * AK;
        const uint32_t ks = sb + (OFF_K + stg * KS_FLOATS) * 4;
        const uint32_t vs = sb + (OFF_V + stg * VS_FLOATS) * 4;
        #pragma unroll
        for (int it = 0; it < 4; it++) {
            const int idx = tid + it * 256;
            const int r = idx >> 4, c4 = idx & 15;
            cp_async16(ks + (r * QSTR + c4 * 4) * 4,
                       &KH[rb + (size_t)(t0 + r) * E_ + c4 * 4]);
            cp_async16(vs + (r * VSTR + c4 * 4) * 4,
                       &VH[rb + (size_t)(t0 + r) * E_ + c4 * 4]);
        }
    };

    loadKV(0, 0); CP_COMMIT();

    for (int kb = 0; kb < nb; kb++) {
        const int stg = kb & 1;
        const int t0  = kb * AK;
        if (kb + 1 < nb) loadKV(kb + 1, stg ^ 1);
        CP_COMMIT();
        CP_WAIT1();
        __syncthreads();

        if (t0 <= wmax) {
            const float* Ks = sm + OFF_K + stg * KS_FLOATS;
            const float* Vs = sm + OFF_V + stg * VS_FLOATS;

            float sc[8][4] = {};
            #pragma unroll
            for (int kk = 0; kk < 8; kk++) {
                uint32_t bf[8][2];
                #pragma unroll
                for (int jj = 0; jj < 8; jj++) {
                    const int n = jj * 8 + g;
                    bf[jj][0] = __float_as_uint(Ks[n * QSTR + kk * 8 + c]);
                    bf[jj][1] = __float_as_uint(Ks[n * QSTR + kk * 8 + c + 4]);
                }
                #pragma unroll
                for (int jj = 0; jj < 8; jj++)
                    mma_tf32(sc[jj], qf[kk], bf[jj]);
            }

            const bool needmask = (t0 + AK - 1) >= wmin;
            #pragma unroll
            for (int jj = 0; jj < 8; jj++) {
                sc[jj][0] *= 0.125f; sc[jj][1] *= 0.125f;
                sc[jj][2] *= 0.125f; sc[jj][3] *= 0.125f;
                if (needmask) {
                    const int cg = t0 + jj * 8 + 2 * c;
                    const int r0 = qrow0, r1 = qrow0 + 8;
                    if (!((cg     < r0) || (r0 == 0 && cg == 0)))     sc[jj][0] = -1e30f;
                    if (!((cg + 1 < r0) || (r0 == 0 && cg + 1 == 0))) sc[jj][1] = -1e30f;
                    if (!(cg     < r1)) sc[jj][2] = -1e30f;
                    if (!(cg + 1 < r1)) sc[jj][3] = -1e30f;
                }
            }

            float mx0 = -1e30f, mx1 = -1e30f;
            #pragma unroll
            for (int jj = 0; jj < 8; jj++) {
                mx0 = fmaxf(mx0, fmaxf(sc[jj][0], sc[jj][1]));
                mx1 = fmaxf(mx1, fmaxf(sc[jj][2], sc[jj][3]));
            }
            mx0 = fmaxf(mx0, __shfl_xor_sync(0xffffffffu, mx0, 1));
            mx0 = fmaxf(mx0, __shfl_xor_sync(0xffffffffu, mx0, 2));
            mx1 = fmaxf(mx1, __shfl_xor_sync(0xffffffffu, mx1, 1));
            mx1 = fmaxf(mx1, __shfl_xor_sync(0xffffffffu, mx1, 2));
            const float mn0 = fmaxf(m0, mx0), mn1 = fmaxf(m1, mx1);
            const float a0 = __expf(m0 - mn0), a1 = __expf(m1 - mn1);
            float s0 = 0.f, s1 = 0.f;
            #pragma unroll
            for (int jj = 0; jj < 8; jj++) {
                sc[jj][0] = __expf(sc[jj][0] - mn0);
                sc[jj][1] = __expf(sc[jj][1] - mn0);
                sc[jj][2] = __expf(sc[jj][2] - mn1);
                sc[jj][3] = __expf(sc[jj][3] - mn1);
                s0 += sc[jj][0] + sc[jj][1];
                s1 += sc[jj][2] + sc[jj][3];
            }
            s0 += __shfl_xor_sync(0xffffffffu, s0, 1);
            s0 += __shfl_xor_sync(0xffffffffu, s0, 2);
            s1 += __shfl_xor_sync(0xffffffffu, s1, 1);
            s1 += __shfl_xor_sync(0xffffffffu, s1, 2);
            l0 = l0 * a0 + s0; l1 = l1 * a1 + s1;
            m0 = mn0; m1 = mn1;
            #pragma unroll
            for (int jj = 0; jj < 8; jj++) {
                o[jj][0] *= a0; o[jj][1] *= a0;
                o[jj][2] *= a1; o[jj][3] *= a1;
            }

            #pragma unroll
            for (int jj = 0; jj < 8; jj++) {
                *(float2*)&Ps[g * VSTR + jj * 8 + 2 * c] =
                    make_float2(to_tf32(sc[jj][0]), to_tf32(sc[jj][1]));
                *(float2*)&Ps[(g + 8) * VSTR + jj * 8 + 2 * c] =
                    make_float2(to_tf32(sc[jj][2]), to_tf32(sc[jj][3]));
            }
            __syncwarp();

            #pragma unroll
            for (int kk = 0; kk < 8; kk++) {
                uint32_t af[4];
                af[0] = __float_as_uint(Ps[g * VSTR + kk * 8 + c]);
                af[1] = __float_as_uint(Ps[(g + 8) * VSTR + kk * 8 + c]);
                af[2] = __float_as_uint(Ps[g * VSTR + kk * 8 + c + 4]);
                af[3] = __float_as_uint(Ps[(g + 8) * VSTR + kk * 8 + c + 4]);
                uint32_t bf[8][2];
                #pragma unroll
                for (int jj = 0; jj < 8; jj++) {
                    bf[jj][0] = __float_as_uint(Vs[(kk * 8 + c) * VSTR + jj * 8 + g]);
                    bf[jj][1] = __float_as_uint(Vs[(kk * 8 + c + 4) * VSTR + jj * 8 + g]);
                }
                #pragma unroll
                for (int jj = 0; jj < 8; jj++)
                    mma_tf32(o[jj], af, bf[jj]);
            }
            __syncwarp();
        }
        __syncthreads();
    }

    const float il0 = 1.f / l0, il1 = 1.f / l1;
    #pragma unroll
    for (int jj = 0; jj < 8; jj++) {
        const int col = jj * 8 + 2 * c;
        *(float2*)&AH[rb + (size_t)qrow0 * E_ + col] =
            make_float2(to_tf32(o[jj][0] * il0), to_tf32(o[jj][1] * il0));
        *(float2*)&AH[rb + (size_t)(qrow0 + 8) * E_ + col] =
            make_float2(to_tf32(o[jj][2] * il1), to_tf32(o[jj][3] * il1));
    }
}

// ===========================================================================
extern "C" void kernel_launch(void* const* d_in, const int* in_sizes, int n_in,
                              void* d_out, int out_size)
{
    const float* q  = (const float*)d_in[0];
    const float* k  = (const float*)d_in[1];
    const float* v  = (const float*)d_in[2];
    const float* Wq = (const float*)d_in[3];
    const float* Wk = (const float*)d_in[4];
    const float* Wv = (const float*)d_in[5];
    const float* bv = (const float*)d_in[6];
    const float* Wo = (const float*)d_in[7];
    const float* bo = (const float*)d_in[8];
    float* out = (float*)d_out;

    float *qh, *kh, *vh, *ah, *qr, *kr, *vr, *wr;
    cudaGetSymbolAddress((void**)&qh, g_qh);
    cudaGetSymbolAddress((void**)&kh, g_kh);
    cudaGetSymbolAddress((void**)&vh, g_vh);
    cudaGetSymbolAddress((void**)&ah, g_ah);
    cudaGetSymbolAddress((void**)&qr, g_qr);
    cudaGetSymbolAddress((void**)&kr, g_kr);
    cudaGetSymbolAddress((void**)&vr, g_vr);
    cudaGetSymbolAddress((void**)&wr, g_wr);

    cudaFuncSetAttribute(gemm_mma, cudaFuncAttributeMaxDynamicSharedMemorySize,
                         GEMM_SMEM);
    cudaFuncSetAttribute(attn_mma, cudaFuncAttributeMaxDynamicSharedMemorySize,
                         ATTN_SMEM);

    // ---- fused tf32 rounding prepass (one launch) ----
    round_all<<<(TOT4 + 255) / 256, 256>>>(
        (const float4*)q, (const float4*)k, (const float4*)v,
        (const float4*)Wq, (const float4*)Wk, (const float4*)Wv, (const float4*)Wo,
        (float4*)qr, (float4*)kr, (float4*)vr, (float4*)wr);

    // ---- fused Q/K/V projections (one launch, z selects problem) ----
    const dim3 ggrd3(M_ / GTM, E_ / GTN, 3);
    gemm_mma<<<ggrd3, 256, GEMM_SMEM>>>(qr, kr, vr,
                                        wr, wr + E_ * E_, wr + 2 * E_ * E_,
                                        qh, kh, vh,
                                        nullptr, nullptr, bv, 1);

    // ---- attention (tensor cores) ----
    const dim3 agrd(S_ / AQ, B_ * H_);
    attn_mma<<<agrd, 256, ATTN_SMEM>>>(qh, kh, vh, ah);

    // ---- output projection (full fp32 out) ----
    const dim3 ggrd1(M_ / GTM, E_ / GTN, 1);
    gemm_mma<<<ggrd1, 256, GEMM_SMEM>>>(ah, ah, ah,
                                        wr + 3 * E_ * E_, nullptr, nullptr,
                                        out, out, out,
                                        bo, bo, bo, 0);
}

// round 7
// speedup vs baseline: 4.2687x; 1.0232x over previous
#include <cuda_runtime.h>
#include <cstdint>

// Problem constants
#define B_   2
#define S_   2048
#define E_   1024
#define H_   16
#define HD_  64
#define M_   (B_ * S_)   // 4096 flattened rows

// Scratch
__device__ float g_qh[M_ * E_];
__device__ float g_kh[M_ * E_];
__device__ float g_vh[M_ * E_];
__device__ float g_ah[M_ * E_];
__device__ float g_qr[M_ * E_];       // tf32-rounded q,k,v
__device__ float g_kr[M_ * E_];
__device__ float g_vr[M_ * E_];
__device__ float g_wr[4 * E_ * E_];   // tf32-rounded Wq,Wk,Wv,Wo

// ===========================================================================
// Helpers
// ===========================================================================
__device__ __forceinline__ uint32_t smem_u32(const void* p) {
    uint32_t a;
    asm("{ .reg .u64 t; cvta.to.shared.u64 t, %1; cvt.u32.u64 %0, t; }"
        : "=r"(a) : "l"(p));
    return a;
}

__device__ __forceinline__ float to_tf32(float x) {
    uint32_t u;
    asm("cvt.rna.tf32.f32 %0, %1;" : "=r"(u) : "f"(x));
    return __uint_as_float(u);
}

__device__ __forceinline__ void cp_async16(uint32_t dst, const void* src) {
    asm volatile("cp.async.cg.shared.global [%0], [%1], 16;"
                 :: "r"(dst), "l"(src) : "memory");
}
#define CP_COMMIT() asm volatile("cp.async.commit_group;" ::: "memory")
#define CP_WAIT1()  asm volatile("cp.async.wait_group 1;" ::: "memory")

__device__ __forceinline__ void mma_tf32(float* d, const uint32_t* a, const uint32_t* b) {
    asm volatile(
        "mma.sync.aligned.m16n8k8.row.col.f32.tf32.tf32.f32 "
        "{%0,%1,%2,%3}, {%4,%5,%6,%7}, {%8,%9}, {%0,%1,%2,%3};"
        : "+f"(d[0]), "+f"(d[1]), "+f"(d[2]), "+f"(d[3])
        : "r"(a[0]), "r"(a[1]), "r"(a[2]), "r"(a[3]), "r"(b[0]), "r"(b[1]));
}

__device__ __forceinline__ void ldsm4(uint32_t* r, uint32_t addr) {
    asm volatile("ldmatrix.sync.aligned.m8n8.x4.shared.b16 {%0,%1,%2,%3}, [%4];"
                 : "=r"(r[0]), "=r"(r[1]), "=r"(r[2]), "=r"(r[3]) : "r"(addr));
}

// ===========================================================================
// Fused tf32 rounding prepass: q,k,v,Wq,Wk,Wv,Wo -> qr,kr,vr,wr (one launch)
// ===========================================================================
#define ACT4 (M_ * E_ / 4)
#define W4   (E_ * E_ / 4)
#define TOT4 (3 * ACT4 + 4 * W4)

__global__ __launch_bounds__(256) void round_all(
    const float4* __restrict__ q, const float4* __restrict__ k,
    const float4* __restrict__ v,
    const float4* __restrict__ Wq, const float4* __restrict__ Wk,
    const float4* __restrict__ Wv, const float4* __restrict__ Wo,
    float4* __restrict__ qr, float4* __restrict__ kr,
    float4* __restrict__ vr, float4* __restrict__ wr)
{
    const long i = (long)blockIdx.x * 256 + threadIdx.x;
    if (i >= TOT4) return;
    const float4* s; float4* d; long off;
    if (i < ACT4)               { s = q;  d = qr; off = i; }
    else if (i < 2L * ACT4)     { s = k;  d = kr; off = i - ACT4; }
    else if (i < 3L * ACT4)     { s = v;  d = vr; off = i - 2L * ACT4; }
    else {
        const long j = i - 3L * ACT4;
        s = (j < W4) ? Wq : (j < 2 * W4) ? Wk : (j < 3 * W4) ? Wv : Wo;
        d = wr + (j / W4) * W4;
        off = j % W4;
    }
    float4 x = s[off];
    x.x = to_tf32(x.x); x.y = to_tf32(x.y);
    x.z = to_tf32(x.z); x.w = to_tf32(x.w);
    d[off] = x;
}

// ===========================================================================
// mma.sync tf32 GEMM:  C[M,1024] = A[M,1024] @ W[1024,1024]^T (+ bias)
// CTA tile 128x128 (2 CTAs/SM), 8 warps (4x2), warp tile 32x64, K-chunk 32,
// 3-stage cp.async, ldmatrix.x4 fragment loads. Inputs already tf32-rounded.
// ===========================================================================
#define GTM   128
#define GTN   128
#define GTK   32
#define NCH   (E_ / GTK)
#define LDS_  36
#define STG_FLOATS ((GTM + GTN) * LDS_)   // 9216
#define STG_BYTES  (STG_FLOATS * 4)       // 36864
#define NSTG  3
#define GEMM_SMEM (NSTG * STG_BYTES)      // 110592

__global__ __launch_bounds__(256, 2) void gemm_mma(
    const float* __restrict__ A0, const float* __restrict__ A1,
    const float* __restrict__ A2,
    const float* __restrict__ W0, const float* __restrict__ W1,
    const float* __restrict__ W2,
    float* __restrict__ C0, float* __restrict__ C1, float* __restrict__ C2,
    const float* __restrict__ b0, const float* __restrict__ b1,
    const float* __restrict__ b2, int round_out)
{
    extern __shared__ float smem[];
    const int tid  = threadIdx.x;
    const int lane = tid & 31;
    const int wid  = tid >> 5;
    const int wm   = wid & 3;    // 4 row-slices of 32
    const int wn   = wid >> 2;   // 2 col-slices of 64

    const int z = blockIdx.z;
    const float* A = (z == 0) ? A0 : (z == 1) ? A1 : A2;
    const float* W = (z == 0) ? W0 : (z == 1) ? W1 : W2;
    float*       C = (z == 0) ? C0 : (z == 1) ? C1 : C2;
    const float* bias = (z == 0) ? b0 : (z == 1) ? b1 : b2;

    const int m0 = blockIdx.x * GTM;
    const int n0 = blockIdx.y * GTN;
    const uint32_t sb = smem_u32(smem);

    // ldmatrix per-lane byte offsets (within a stage)
    uint32_t aoff[2], boff[4];
    #pragma unroll
    for (int ii = 0; ii < 2; ii++)
        aoff[ii] = ((wm * 32 + ii * 16 + (lane & 15)) * LDS_ + ((lane >> 4) << 2)) * 4;
    #pragma unroll
    for (int jp = 0; jp < 4; jp++)
        boff[jp] = (GTM * LDS_
                    + (wn * 64 + jp * 16 + ((lane >> 4) << 3) + (lane & 7)) * LDS_
                    + ((lane >> 3) & 1) * 4) * 4;

    float acc[2][8][4] = {};

    auto load_chunk = [&](int ch, int stg) {
        const int k0 = ch * GTK;
        const uint32_t as = sb + stg * STG_BYTES;
        const uint32_t bs = as + GTM * LDS_ * 4;
        #pragma unroll
        for (int it = 0; it < 4; it++) {
            const int idx = tid + it * 256;
            const int r = idx >> 3, c4 = idx & 7;
            cp_async16(as + r * (LDS_ * 4) + c4 * 16,
                       A + (size_t)(m0 + r) * E_ + k0 + c4 * 4);
        }
        #pragma unroll
        for (int it = 0; it < 4; it++) {
            const int idx = tid + it * 256;
            const int r = idx >> 3, c4 = idx & 7;
            cp_async16(bs + r * (LDS_ * 4) + c4 * 16,
                       W + (size_t)(n0 + r) * E_ + k0 + c4 * 4);
        }
    };

    load_chunk(0, 0); CP_COMMIT();
    load_chunk(1, 1); CP_COMMIT();

    for (int i = 0; i < NCH; i++) {
        CP_WAIT1();
        __syncthreads();
        if (i + 2 < NCH) load_chunk(i + 2, (i + 2) % NSTG);
        CP_COMMIT();

        const uint32_t su = sb + (i % NSTG) * STG_BYTES;

        #pragma unroll
        for (int kk = 0; kk < 4; kk++) {
            const uint32_t kb = su + kk * 32;   // k8 step = 8 floats = 32 bytes
            uint32_t af[2][4], bf[4][4];
            #pragma unroll
            for (int ii = 0; ii < 2; ii++) ldsm4(af[ii], kb + aoff[ii]);
            #pragma unroll
            for (int jp = 0; jp < 4; jp++) ldsm4(bf[jp], kb + boff[jp]);
            #pragma unroll
            for (int ii = 0; ii < 2; ii++)
                #pragma unroll
                for (int jp = 0; jp < 4; jp++) {
                    mma_tf32(acc[ii][2 * jp],     af[ii], &bf[jp][0]);
                    mma_tf32(acc[ii][2 * jp + 1], af[ii], &bf[jp][2]);
                }
        }
    }

    const int g = lane >> 2;
    const int c = lane & 3;
    #pragma unroll
    for (int ii = 0; ii < 2; ii++) {
        const int r0 = m0 + wm * 32 + ii * 16 + g;
        #pragma unroll
        for (int jj = 0; jj < 8; jj++) {
            const int cc = n0 + wn * 64 + jj * 8 + 2 * c;
            float bx = 0.f, by = 0.f;
            if (bias) { bx = bias[cc]; by = bias[cc + 1]; }
            float2 v0 = make_float2(acc[ii][jj][0] + bx, acc[ii][jj][1] + by);
            float2 v1 = make_float2(acc[ii][jj][2] + bx, acc[ii][jj][3] + by);
            if (round_out) {
                v0.x = to_tf32(v0.x); v0.y = to_tf32(v0.y);
                v1.x = to_tf32(v1.x); v1.y = to_tf32(v1.y);
            }
            *(float2*)&C[(size_t)r0 * E_ + cc]       = v0;
            *(float2*)&C[(size_t)(r0 + 8) * E_ + cc] = v1;
        }
    }
}

// ===========================================================================
// Tensor-core flash attention (tf32 mma), strict-causal with (0,0) exception.
// CTA = (b,h) x 128 q-rows; 8 warps x 16 rows; K/V blocks of 64, cp.async x2.
// ===========================================================================
#define AQ    128
#define AK    64
#define QSTR  68
#define VSTR  72
#define KS_FLOATS (AK * QSTR)
#define VS_FLOATS (AK * VSTR)
#define QP_FLOATS (8 * 16 * VSTR)
#define OFF_K  QP_FLOATS
#define OFF_V  (OFF_K + 2 * KS_FLOATS)
#define ATTN_SMEM ((OFF_V + 2 * VS_FLOATS) * 4)

__global__ __launch_bounds__(256, 1) void attn_mma(
    const float* __restrict__ QH, const float* __restrict__ KH,
    const float* __restrict__ VH, float* __restrict__ AH)
{
    extern __shared__ float sm[];
    const int tid  = threadIdx.x;
    const int lane = tid & 31;
    const int w    = tid >> 5;
    const int g    = lane >> 2;
    const int c    = lane & 3;
    const int qi   = (int)(gridDim.x - 1) - (int)blockIdx.x;
    const int bh   = blockIdx.y;
    const int b    = bh >> 4;
    const int h    = bh & 15;
    const int qbase = qi * AQ;
    const size_t rb = (size_t)b * S_ * E_ + (size_t)h * HD_;

    float* Qs = sm;
    float* Ps = sm + w * (16 * VSTR);
    const uint32_t sb = smem_u32(sm);

    #pragma unroll
    for (int it = 0; it < 8; it++) {
        const int idx = tid + it * 256;
        const int r = idx >> 4, c4 = idx & 15;
        float4 v = *(const float4*)&QH[rb + (size_t)(qbase + r) * E_ + c4 * 4];
        *(float4*)&Qs[r * QSTR + c4 * 4] = v;
    }
    __syncthreads();
    uint32_t qf[8][4];
    {
        const float* qw = Qs + (w * 16) * QSTR;
        #pragma unroll
        for (int kk = 0; kk < 8; kk++) {
            qf[kk][0] = __float_as_uint(qw[g * QSTR + kk * 8 + c]);
            qf[kk][1] = __float_as_uint(qw[(g + 8) * QSTR + kk * 8 + c]);
            qf[kk][2] = __float_as_uint(qw[g * QSTR + kk * 8 + c + 4]);
            qf[kk][3] = __float_as_uint(qw[(g + 8) * QSTR + kk * 8 + c + 4]);
        }
    }
    __syncthreads();

    float o[8][4] = {};
    float m0 = -1e30f, m1 = -1e30f, l0 = 0.f, l1 = 0.f;
    const int nb = 2 * qi + 2;
    const int qrow0 = qbase + w * 16 + g;
    const int wmin  = qbase + w * 16;
    const int wmax  = wmin + 15;

    auto loadKV = [&](int kb, int stg) {
        const int t0 = kb * AK;
        const uint32_t ks = sb + (OFF_K + stg * KS_FLOATS) * 4;
        const uint32_t vs = sb + (OFF_V + stg * VS_FLOATS) * 4;
        #pragma unroll
        for (int it = 0; it < 4; it++) {
            const int idx = tid + it * 256;
            const int r = idx >> 4, c4 = idx & 15;
            cp_async16(ks + (r * QSTR + c4 * 4) * 4,
                       &KH[rb + (size_t)(t0 + r) * E_ + c4 * 4]);
            cp_async16(vs + (r * VSTR + c4 * 4) * 4,
                       &VH[rb + (size_t)(t0 + r) * E_ + c4 * 4]);
        }
    };

    loadKV(0, 0); CP_COMMIT();

    for (int kb = 0; kb < nb; kb++) {
        const int stg = kb & 1;
        const int t0  = kb * AK;
        if (kb + 1 < nb) loadKV(kb + 1, stg ^ 1);
        CP_COMMIT();
        CP_WAIT1();
        __syncthreads();

        if (t0 <= wmax) {
            const float* Ks = sm + OFF_K + stg * KS_FLOATS;
            const float* Vs = sm + OFF_V + stg * VS_FLOATS;

            float sc[8][4] = {};
            #pragma unroll
            for (int kk = 0; kk < 8; kk++) {
                uint32_t bf[8][2];
                #pragma unroll
                for (int jj = 0; jj < 8; jj++) {
                    const int n = jj * 8 + g;
                    bf[jj][0] = __float_as_uint(Ks[n * QSTR + kk * 8 + c]);
                    bf[jj][1] = __float_as_uint(Ks[n * QSTR + kk * 8 + c + 4]);
                }
                #pragma unroll
                for (int jj = 0; jj < 8; jj++)
                    mma_tf32(sc[jj], qf[kk], bf[jj]);
            }

            const bool needmask = (t0 + AK - 1) >= wmin;
            #pragma unroll
            for (int jj = 0; jj < 8; jj++) {
                sc[jj][0] *= 0.125f; sc[jj][1] *= 0.125f;
                sc[jj][2] *= 0.125f; sc[jj][3] *= 0.125f;
                if (needmask) {
                    const int cg = t0 + jj * 8 + 2 * c;
                    const int r0 = qrow0, r1 = qrow0 + 8;
                    if (!((cg     < r0) || (r0 == 0 && cg == 0)))     sc[jj][0] = -1e30f;
                    if (!((cg + 1 < r0) || (r0 == 0 && cg + 1 == 0))) sc[jj][1] = -1e30f;
                    if (!(cg     < r1)) sc[jj][2] = -1e30f;
                    if (!(cg + 1 < r1)) sc[jj][3] = -1e30f;
                }
            }

            float mx0 = -1e30f, mx1 = -1e30f;
            #pragma unroll
            for (int jj = 0; jj < 8; jj++) {
                mx0 = fmaxf(mx0, fmaxf(sc[jj][0], sc[jj][1]));
                mx1 = fmaxf(mx1, fmaxf(sc[jj][2], sc[jj][3]));
            }
            mx0 = fmaxf(mx0, __shfl_xor_sync(0xffffffffu, mx0, 1));
            mx0 = fmaxf(mx0, __shfl_xor_sync(0xffffffffu, mx0, 2));
            mx1 = fmaxf(mx1, __shfl_xor_sync(0xffffffffu, mx1, 1));
            mx1 = fmaxf(mx1, __shfl_xor_sync(0xffffffffu, mx1, 2));
            const float mn0 = fmaxf(m0, mx0), mn1 = fmaxf(m1, mx1);
            const float a0 = __expf(m0 - mn0), a1 = __expf(m1 - mn1);
            float s0 = 0.f, s1 = 0.f;
            #pragma unroll
            for (int jj = 0; jj < 8; jj++) {
                sc[jj][0] = __expf(sc[jj][0] - mn0);
                sc[jj][1] = __expf(sc[jj][1] - mn0);
                sc[jj][2] = __expf(sc[jj][2] - mn1);
                sc[jj][3] = __expf(sc[jj][3] - mn1);
                s0 += sc[jj][0] + sc[jj][1];
                s1 += sc[jj][2] + sc[jj][3];
            }
            s0 += __shfl_xor_sync(0xffffffffu, s0, 1);
            s0 += __shfl_xor_sync(0xffffffffu, s0, 2);
            s1 += __shfl_xor_sync(0xffffffffu, s1, 1);
            s1 += __shfl_xor_sync(0xffffffffu, s1, 2);
            l0 = l0 * a0 + s0; l1 = l1 * a1 + s1;
            m0 = mn0; m1 = mn1;
            #pragma unroll
            for (int jj = 0; jj < 8; jj++) {
                o[jj][0] *= a0; o[jj][1] *= a0;
                o[jj][2] *= a1; o[jj][3] *= a1;
            }

            #pragma unroll
            for (int jj = 0; jj < 8; jj++) {
                *(float2*)&Ps[g * VSTR + jj * 8 + 2 * c] =
                    make_float2(to_tf32(sc[jj][0]), to_tf32(sc[jj][1]));
                *(float2*)&Ps[(g + 8) * VSTR + jj * 8 + 2 * c] =
                    make_float2(to_tf32(sc[jj][2]), to_tf32(sc[jj][3]));
            }
            __syncwarp();

            #pragma unroll
            for (int kk = 0; kk < 8; kk++) {
                uint32_t af[4];
                af[0] = __float_as_uint(Ps[g * VSTR + kk * 8 + c]);
                af[1] = __float_as_uint(Ps[(g + 8) * VSTR + kk * 8 + c]);
                af[2] = __float_as_uint(Ps[g * VSTR + kk * 8 + c + 4]);
                af[3] = __float_as_uint(Ps[(g + 8) * VSTR + kk * 8 + c + 4]);
                uint32_t bf[8][2];
                #pragma unroll
                for (int jj = 0; jj < 8; jj++) {
                    bf[jj][0] = __float_as_uint(Vs[(kk * 8 + c) * VSTR + jj * 8 + g]);
                    bf[jj][1] = __float_as_uint(Vs[(kk * 8 + c + 4) * VSTR + jj * 8 + g]);
                }
                #pragma unroll
                for (int jj = 0; jj < 8; jj++)
                    mma_tf32(o[jj], af, bf[jj]);
            }
            __syncwarp();
        }
        __syncthreads();
    }

    const float il0 = 1.f / l0, il1 = 1.f / l1;
    #pragma unroll
    for (int jj = 0; jj < 8; jj++) {
        const int col = jj * 8 + 2 * c;
        *(float2*)&AH[rb + (size_t)qrow0 * E_ + col] =
            make_float2(to_tf32(o[jj][0] * il0), to_tf32(o[jj][1] * il0));
        *(float2*)&AH[rb + (size_t)(qrow0 + 8) * E_ + col] =
            make_float2(to_tf32(o[jj][2] * il1), to_tf32(o[jj][3] * il1));
    }
}

// ===========================================================================
extern "C" void kernel_launch(void* const* d_in, const int* in_sizes, int n_in,
                              void* d_out, int out_size)
{
    const float* q  = (const float*)d_in[0];
    const float* k  = (const float*)d_in[1];
    const float* v  = (const float*)d_in[2];
    const float* Wq = (const float*)d_in[3];
    const float* Wk = (const float*)d_in[4];
    const float* Wv = (const float*)d_in[5];
    const float* bv = (const float*)d_in[6];
    const float* Wo = (const float*)d_in[7];
    const float* bo = (const float*)d_in[8];
    float* out = (float*)d_out;

    float *qh, *kh, *vh, *ah, *qr, *kr, *vr, *wr;
    cudaGetSymbolAddress((void**)&qh, g_qh);
    cudaGetSymbolAddress((void**)&kh, g_kh);
    cudaGetSymbolAddress((void**)&vh, g_vh);
    cudaGetSymbolAddress((void**)&ah, g_ah);
    cudaGetSymbolAddress((void**)&qr, g_qr);
    cudaGetSymbolAddress((void**)&kr, g_kr);
    cudaGetSymbolAddress((void**)&vr, g_vr);
    cudaGetSymbolAddress((void**)&wr, g_wr);

    cudaFuncSetAttribute(gemm_mma, cudaFuncAttributeMaxDynamicSharedMemorySize,
                         GEMM_SMEM);
    cudaFuncSetAttribute(attn_mma, cudaFuncAttributeMaxDynamicSharedMemorySize,
                         ATTN_SMEM);

    // ---- fused tf32 rounding prepass (one launch) ----
    round_all<<<(TOT4 + 255) / 256, 256>>>(
        (const float4*)q, (const float4*)k, (const float4*)v,
        (const float4*)Wq, (const float4*)Wk, (const float4*)Wv, (const float4*)Wo,
        (float4*)qr, (float4*)kr, (float4*)vr, (float4*)wr);

    // ---- fused Q/K/V projections (one launch, z selects problem) ----
    const dim3 ggrd3(M_ / GTM, E_ / GTN, 3);   // (32, 8, 3)
    gemm_mma<<<ggrd3, 256, GEMM_SMEM>>>(qr, kr, vr,
                                        wr, wr + E_ * E_, wr + 2 * E_ * E_,
                                        qh, kh, vh,
                                        nullptr, nullptr, bv, 1);

    // ---- attention (tensor cores) ----
    const dim3 agrd(S_ / AQ, B_ * H_);
    attn_mma<<<agrd, 256, ATTN_SMEM>>>(qh, kh, vh, ah);

    // ---- output projection (full fp32 out) ----
    const dim3 ggrd1(M_ / GTM, E_ / GTN, 1);   // (32, 8)
    gemm_mma<<<ggrd1, 256, GEMM_SMEM>>>(ah, ah, ah,
                                        wr + 3 * E_ * E_, nullptr, nullptr,
                                        out, out, out,
                                        bo, bo, bo, 0);
}

// round 8
// speedup vs baseline: 7.9884x; 1.8714x over previous
#include <cuda_runtime.h>
#include <cuda_fp16.h>
#include <cstdint>

// Problem constants
#define B_   2
#define S_   2048
#define E_   1024
#define H_   16
#define HD_  64
#define M_   (B_ * S_)   // 4096 flattened rows

// Scratch (fp16)
__device__ __half g_qc[M_ * E_];       // fp16 q,k,v inputs
__device__ __half g_kc[M_ * E_];
__device__ __half g_vc[M_ * E_];
__device__ __half g_wc[4 * E_ * E_];   // fp16 Wq,Wk,Wv,Wo
__device__ __half g_qh[M_ * E_];       // projected Q,K,V (fp16)
__device__ __half g_kh[M_ * E_];
__device__ __half g_vh[M_ * E_];
__device__ __half g_ah[M_ * E_];       // attention output (fp16)

// ===========================================================================
// Helpers
// ===========================================================================
__device__ __forceinline__ uint32_t smem_u32(const void* p) {
    uint32_t a;
    asm("{ .reg .u64 t; cvta.to.shared.u64 t, %1; cvt.u32.u64 %0, t; }"
        : "=r"(a) : "l"(p));
    return a;
}

__device__ __forceinline__ void cp_async16(uint32_t dst, const void* src) {
    asm volatile("cp.async.cg.shared.global [%0], [%1], 16;"
                 :: "r"(dst), "l"(src) : "memory");
}
#define CP_COMMIT() asm volatile("cp.async.commit_group;" ::: "memory")
#define CP_WAIT1()  asm volatile("cp.async.wait_group 1;" ::: "memory")

__device__ __forceinline__ void mma_f16(float* d, const uint32_t* a, const uint32_t* b) {
    asm volatile(
        "mma.sync.aligned.m16n8k16.row.col.f32.f16.f16.f32 "
        "{%0,%1,%2,%3}, {%4,%5,%6,%7}, {%8,%9}, {%0,%1,%2,%3};"
        : "+f"(d[0]), "+f"(d[1]), "+f"(d[2]), "+f"(d[3])
        : "r"(a[0]), "r"(a[1]), "r"(a[2]), "r"(a[3]), "r"(b[0]), "r"(b[1]));
}

__device__ __forceinline__ void ldsm4(uint32_t* r, uint32_t addr) {
    asm volatile("ldmatrix.sync.aligned.m8n8.x4.shared.b16 {%0,%1,%2,%3}, [%4];"
                 : "=r"(r[0]), "=r"(r[1]), "=r"(r[2]), "=r"(r[3]) : "r"(addr));
}
__device__ __forceinline__ void ldsm4t(uint32_t* r, uint32_t addr) {
    asm volatile("ldmatrix.sync.aligned.m8n8.x4.trans.shared.b16 {%0,%1,%2,%3}, [%4];"
                 : "=r"(r[0]), "=r"(r[1]), "=r"(r[2]), "=r"(r[3]) : "r"(addr));
}

__device__ __forceinline__ uint32_t h2pack(float a, float b) {
    __half2 h = __floats2half2_rn(a, b);
    return *(uint32_t*)&h;
}

// ===========================================================================
// fp32 -> fp16 conversion prepass (one launch; groups of 8 floats)
// ===========================================================================
#define ACT8 (M_ * E_ / 8)   // 524288
#define W8   (E_ * E_ / 8)   // 131072
#define TOT8 (3 * ACT8 + 4 * W8)

__global__ __launch_bounds__(256) void round_h_all(
    const float4* __restrict__ q, const float4* __restrict__ k,
    const float4* __restrict__ v,
    const float4* __restrict__ Wq, const float4* __restrict__ Wk,
    const float4* __restrict__ Wv, const float4* __restrict__ Wo,
    __half* __restrict__ qc, __half* __restrict__ kc,
    __half* __restrict__ vc, __half* __restrict__ wc)
{
    const long i = (long)blockIdx.x * 256 + threadIdx.x;
    if (i >= TOT8) return;
    const float4* s; __half* d; long off;
    if (i < ACT8)            { s = q; d = qc; off = i; }
    else if (i < 2L * ACT8)  { s = k; d = kc; off = i - ACT8; }
    else if (i < 3L * ACT8)  { s = v; d = vc; off = i - 2L * ACT8; }
    else {
        const long j = i - 3L * ACT8;
        s = (j < W8) ? Wq : (j < 2 * W8) ? Wk : (j < 3 * W8) ? Wv : Wo;
        d = wc + (j / W8) * (E_ * (long)E_);
        off = j % W8;
    }
    float4 u = s[2 * off], w = s[2 * off + 1];
    uint4 o;
    o.x = h2pack(u.x, u.y); o.y = h2pack(u.z, u.w);
    o.z = h2pack(w.x, w.y); o.w = h2pack(w.z, w.w);
    *(uint4*)(d + off * 8) = o;
}

// ===========================================================================
// mma.sync fp16 GEMM:  C[M,1024] = A[M,1024] @ W[1024,1024]^T (+ bias)
// CTA 128x128 (2 CTAs/SM), 8 warps (4x2), warp tile 32x64, K-chunk 64 halves,
// 3-stage cp.async, ldmatrix.x4 frag loads. Output fp16 (Ch) or fp32 (Cf).
// ===========================================================================
#define GTM   128
#define GTN   128
#define GTK   64
#define NCH   (E_ / GTK)                  // 16
#define STRH  72
#define STRB  144
#define AB_   (GTM * STRB)                // 18432
#define STG_BYTES (AB_ + GTN * STRB)      // 36864
#define NSTG  3
#define GEMM_SMEM (NSTG * STG_BYTES)      // 110592

__global__ __launch_bounds__(256, 2) void gemm_mma(
    const __half* __restrict__ A0, const __half* __restrict__ A1,
    const __half* __restrict__ A2,
    const __half* __restrict__ W0, const __half* __restrict__ W1,
    const __half* __restrict__ W2,
    float* __restrict__ Cf,
    __half* __restrict__ Ch0, __half* __restrict__ Ch1, __half* __restrict__ Ch2,
    const float* __restrict__ b0, const float* __restrict__ b1,
    const float* __restrict__ b2)
{
    extern __shared__ char smem[];
    const int tid  = threadIdx.x;
    const int lane = tid & 31;
    const int wid  = tid >> 5;
    const int wm   = wid & 3;
    const int wn   = wid >> 2;

    const int z = blockIdx.z;
    const __half* A = (z == 0) ? A0 : (z == 1) ? A1 : A2;
    const __half* W = (z == 0) ? W0 : (z == 1) ? W1 : W2;
    __half* Ch = (z == 0) ? Ch0 : (z == 1) ? Ch1 : Ch2;
    const float* bias = (z == 0) ? b0 : (z == 1) ? b1 : b2;

    const int m0 = blockIdx.x * GTM;
    const int n0 = blockIdx.y * GTN;
    const uint32_t sb = smem_u32(smem);

    uint32_t aoff[2], boff[4];
    #pragma unroll
    for (int ii = 0; ii < 2; ii++)
        aoff[ii] = (wm * 32 + ii * 16 + (lane & 15)) * STRB + (lane >> 4) * 16;
    #pragma unroll
    for (int jp = 0; jp < 4; jp++)
        boff[jp] = AB_ + (wn * 64 + jp * 16 + ((lane >> 4) << 3) + (lane & 7)) * STRB
                 + ((lane >> 3) & 1) * 16;

    float acc[2][8][4] = {};

    auto load_chunk = [&](int ch, int stg) {
        const int k0 = ch * GTK;
        const uint32_t as = sb + stg * STG_BYTES;
        const uint32_t bs = as + AB_;
        #pragma unroll
        for (int it = 0; it < 4; it++) {
            const int idx = tid + it * 256;
            const int r = idx >> 3, c8 = idx & 7;
            cp_async16(as + r * STRB + c8 * 16,
                       A + (size_t)(m0 + r) * E_ + k0 + c8 * 8);
        }
        #pragma unroll
        for (int it = 0; it < 4; it++) {
            const int idx = tid + it * 256;
            const int r = idx >> 3, c8 = idx & 7;
            cp_async16(bs + r * STRB + c8 * 16,
                       W + (size_t)(n0 + r) * E_ + k0 + c8 * 8);
        }
    };

    load_chunk(0, 0); CP_COMMIT();
    load_chunk(1, 1); CP_COMMIT();

    for (int i = 0; i < NCH; i++) {
        CP_WAIT1();
        __syncthreads();
        if (i + 2 < NCH) load_chunk(i + 2, (i + 2) % NSTG);
        CP_COMMIT();

        const uint32_t su = sb + (i % NSTG) * STG_BYTES;

        #pragma unroll
        for (int kk = 0; kk < 4; kk++) {     // 4 x k16 = 64 halves
            const uint32_t kb = su + kk * 32;
            uint32_t af[2][4], bf[4][4];
            #pragma unroll
            for (int ii = 0; ii < 2; ii++) ldsm4(af[ii], kb + aoff[ii]);
            #pragma unroll
            for (int jp = 0; jp < 4; jp++) ldsm4(bf[jp], kb + boff[jp]);
            // bf[jp] = { n-grp(2jp):b0,b1 , n-grp(2jp+1):b0,b1 } = r0,r1,r2,r3
            #pragma unroll
            for (int ii = 0; ii < 2; ii++)
                #pragma unroll
                for (int jp = 0; jp < 4; jp++) {
                    mma_f16(acc[ii][2 * jp],     af[ii], &bf[jp][0]);
                    mma_f16(acc[ii][2 * jp + 1], af[ii], &bf[jp][2]);
                }
        }
    }

    const int g = lane >> 2;
    const int c = lane & 3;
    #pragma unroll
    for (int ii = 0; ii < 2; ii++) {
        const int r0 = m0 + wm * 32 + ii * 16 + g;
        #pragma unroll
        for (int jj = 0; jj < 8; jj++) {
            const int cc = n0 + wn * 64 + jj * 8 + 2 * c;
            float bx = 0.f, by = 0.f;
            if (bias) { bx = bias[cc]; by = bias[cc + 1]; }
            const float v00 = acc[ii][jj][0] + bx, v01 = acc[ii][jj][1] + by;
            const float v10 = acc[ii][jj][2] + bx, v11 = acc[ii][jj][3] + by;
            if (Ch) {
                *(uint32_t*)&Ch[(size_t)r0 * E_ + cc]       = h2pack(v00, v01);
                *(uint32_t*)&Ch[(size_t)(r0 + 8) * E_ + cc] = h2pack(v10, v11);
            } else {
                *(float2*)&Cf[(size_t)r0 * E_ + cc]       = make_float2(v00, v01);
                *(float2*)&Cf[(size_t)(r0 + 8) * E_ + cc] = make_float2(v10, v11);
            }
        }
    }
}

// ===========================================================================
// fp16 tensor-core flash attention, strict-causal with (0,0) exception.
// CTA = (b,h) x 128 q-rows; 8 warps x 16 rows; K/V blocks of 64.
// P stays in registers (D-frag -> A-frag repack); V loaded via ldmatrix.trans.
// ===========================================================================
#define AQ    128
#define AK    64
#define ASTR  72                              // halves; 144 B rows
#define QBYTES (AQ * 144)                     // 18432
#define KVBYTES (AK * 144)                    // 9216
#define OFF_K  QBYTES
#define OFF_V  (OFF_K + 2 * KVBYTES)
#define ATTN_SMEM (OFF_V + 2 * KVBYTES)       // 55296

__global__ __launch_bounds__(256, 2) void attn_mma(
    const __half* __restrict__ QH, const __half* __restrict__ KH,
    const __half* __restrict__ VH, __half* __restrict__ AH)
{
    extern __shared__ char smc[];
    const int tid  = threadIdx.x;
    const int lane = tid & 31;
    const int w    = tid >> 5;
    const int g    = lane >> 2;
    const int c    = lane & 3;
    const int qi   = (int)(gridDim.x - 1) - (int)blockIdx.x;  // heavy tiles first
    const int bh   = blockIdx.y;
    const int b    = bh >> 4;
    const int h    = bh & 15;
    const int qbase = qi * AQ;
    const size_t rb = (size_t)b * S_ * E_ + (size_t)h * HD_;

    const uint32_t sb = smem_u32(smc);

    // ---- load Q tile (128 x 64 halves) ----
    #pragma unroll
    for (int it = 0; it < 4; it++) {
        const int idx = tid + it * 256;       // 1024 x 16B
        const int r = idx >> 3, c8 = idx & 7;
        uint4 v = *(const uint4*)&QH[rb + (size_t)(qbase + r) * E_ + c8 * 8];
        *(uint4*)(smc + r * 144 + c8 * 16) = v;
    }
    __syncthreads();

    // ---- Q fragments: 4 k16 steps ----
    uint32_t qf[4][4];
    #pragma unroll
    for (int kk = 0; kk < 4; kk++)
        ldsm4(qf[kk], sb + (w * 16 + (lane & 15)) * 144 + kk * 32 + (lane >> 4) * 16);
    __syncthreads();

    float o[8][4] = {};
    float m0 = -1e30f, m1 = -1e30f, l0 = 0.f, l1 = 0.f;
    const int nb = 2 * qi + 2;
    const int qrow0 = qbase + w * 16 + g;
    const int wmin  = qbase + w * 16;
    const int wmax  = wmin + 15;

    // K ldsm offsets (non-trans): per jp covers 16 keys
    uint32_t koff[4], voff[4];
    #pragma unroll
    for (int jp = 0; jp < 4; jp++)
        koff[jp] = (jp * 16 + ((lane >> 4) << 3) + (lane & 7)) * 144
                 + ((lane >> 3) & 1) * 16;
    // V ldsm.trans offsets: per jp covers 16 d-cols; row = token
    {
        const int qd = lane >> 3;     // 0..3
        #pragma unroll
        for (int jp = 0; jp < 4; jp++)
            voff[jp] = (((qd & 1) << 3) + (lane & 7)) * 144
                     + jp * 32 + ((qd >> 1) << 4);
    }

    auto loadKV = [&](int kb, int stg) {
        const int t0 = kb * AK;
        const uint32_t ks = sb + OFF_K + stg * KVBYTES;
        const uint32_t vs = sb + OFF_V + stg * KVBYTES;
        #pragma unroll
        for (int it = 0; it < 2; it++) {
            const int idx = tid + it * 256;   // 512 x 16B each
            const int r = idx >> 3, c8 = idx & 7;
            cp_async16(ks + r * 144 + c8 * 16,
                       &KH[rb + (size_t)(t0 + r) * E_ + c8 * 8]);
            cp_async16(vs + r * 144 + c8 * 16,
                       &VH[rb + (size_t)(t0 + r) * E_ + c8 * 8]);
        }
    };

    loadKV(0, 0); CP_COMMIT();

    for (int kb = 0; kb < nb; kb++) {
        const int stg = kb & 1;
        const int t0  = kb * AK;
        if (kb + 1 < nb) loadKV(kb + 1, stg ^ 1);
        CP_COMMIT();
        CP_WAIT1();
        __syncthreads();

        if (t0 <= wmax) {
            const uint32_t ks = sb + OFF_K + stg * KVBYTES;
            const uint32_t vs = sb + OFF_V + stg * KVBYTES;

            // ---- S = Q @ K^T ----
            float sc[8][4] = {};
            #pragma unroll
            for (int kk = 0; kk < 4; kk++) {
                uint32_t kf[4][4];
                #pragma unroll
                for (int jp = 0; jp < 4; jp++) ldsm4(kf[jp], ks + koff[jp] + kk * 32);
                #pragma unroll
                for (int jp = 0; jp < 4; jp++) {
                    mma_f16(sc[2 * jp],     qf[kk], &kf[jp][0]);
                    mma_f16(sc[2 * jp + 1], qf[kk], &kf[jp][2]);
                }
            }

            // ---- scale + causal mask ----
            const bool needmask = (t0 + AK - 1) >= wmin;
            #pragma unroll
            for (int jj = 0; jj < 8; jj++) {
                sc[jj][0] *= 0.125f; sc[jj][1] *= 0.125f;
                sc[jj][2] *= 0.125f; sc[jj][3] *= 0.125f;
                if (needmask) {
                    const int cg = t0 + jj * 8 + 2 * c;
                    const int r0 = qrow0, r1 = qrow0 + 8;
                    if (!((cg     < r0) || (r0 == 0 && cg == 0)))     sc[jj][0] = -1e30f;
                    if (!((cg + 1 < r0) || (r0 == 0 && cg + 1 == 0))) sc[jj][1] = -1e30f;
                    if (!(cg     < r1)) sc[jj][2] = -1e30f;
                    if (!(cg + 1 < r1)) sc[jj][3] = -1e30f;
                }
            }

            // ---- online softmax ----
            float mx0 = -1e30f, mx1 = -1e30f;
            #pragma unroll
            for (int jj = 0; jj < 8; jj++) {
                mx0 = fmaxf(mx0, fmaxf(sc[jj][0], sc[jj][1]));
                mx1 = fmaxf(mx1, fmaxf(sc[jj][2], sc[jj][3]));
            }
            mx0 = fmaxf(mx0, __shfl_xor_sync(0xffffffffu, mx0, 1));
            mx0 = fmaxf(mx0, __shfl_xor_sync(0xffffffffu, mx0, 2));
            mx1 = fmaxf(mx1, __shfl_xor_sync(0xffffffffu, mx1, 1));
            mx1 = fmaxf(mx1, __shfl_xor_sync(0xffffffffu, mx1, 2));
            const float mn0 = fmaxf(m0, mx0), mn1 = fmaxf(m1, mx1);
            const float a0 = __expf(m0 - mn0), a1 = __expf(m1 - mn1);
            float s0 = 0.f, s1 = 0.f;
            #pragma unroll
            for (int jj = 0; jj < 8; jj++) {
                sc[jj][0] = __expf(sc[jj][0] - mn0);
                sc[jj][1] = __expf(sc[jj][1] - mn0);
                sc[jj][2] = __expf(sc[jj][2] - mn1);
                sc[jj][3] = __expf(sc[jj][3] - mn1);
                s0 += sc[jj][0] + sc[jj][1];
                s1 += sc[jj][2] + sc[jj][3];
            }
            s0 += __shfl_xor_sync(0xffffffffu, s0, 1);
            s0 += __shfl_xor_sync(0xffffffffu, s0, 2);
            s1 += __shfl_xor_sync(0xffffffffu, s1, 1);
            s1 += __shfl_xor_sync(0xffffffffu, s1, 2);
            l0 = l0 * a0 + s0; l1 = l1 * a1 + s1;
            m0 = mn0; m1 = mn1;
            #pragma unroll
            for (int jj = 0; jj < 8; jj++) {
                o[jj][0] *= a0; o[jj][1] *= a0;
                o[jj][2] *= a1; o[jj][3] *= a1;
            }

            // ---- O += P @ V  (P repacked from D-frags; V via ldmatrix.trans) ----
            #pragma unroll
            for (int kk = 0; kk < 4; kk++) {
                uint32_t pf[4];
                pf[0] = h2pack(sc[2 * kk][0],     sc[2 * kk][1]);
                pf[1] = h2pack(sc[2 * kk][2],     sc[2 * kk][3]);
                pf[2] = h2pack(sc[2 * kk + 1][0], sc[2 * kk + 1][1]);
                pf[3] = h2pack(sc[2 * kk + 1][2], sc[2 * kk + 1][3]);
                uint32_t vf[4][4];
                #pragma unroll
                for (int jp = 0; jp < 4; jp++)
                    ldsm4t(vf[jp], vs + voff[jp] + kk * 16 * 144);
                #pragma unroll
                for (int jp = 0; jp < 4; jp++) {
                    mma_f16(o[2 * jp],     pf, &vf[jp][0]);
                    mma_f16(o[2 * jp + 1], pf, &vf[jp][2]);
                }
            }
        }
        __syncthreads();
    }

    // ---- epilogue: normalize, convert to fp16 for Wo GEMM ----
    const float il0 = 1.f / l0, il1 = 1.f / l1;
    #pragma unroll
    for (int jj = 0; jj < 8; jj++) {
        const int col = jj * 8 + 2 * c;
        *(uint32_t*)&AH[rb + (size_t)qrow0 * E_ + col] =
            h2pack(o[jj][0] * il0, o[jj][1] * il0);
        *(uint32_t*)&AH[rb + (size_t)(qrow0 + 8) * E_ + col] =
            h2pack(o[jj][2] * il1, o[jj][3] * il1);
    }
}

// ===========================================================================
extern "C" void kernel_launch(void* const* d_in, const int* in_sizes, int n_in,
                              void* d_out, int out_size)
{
    const float* q  = (const float*)d_in[0];
    const float* k  = (const float*)d_in[1];
    const float* v  = (const float*)d_in[2];
    const float* Wq = (const float*)d_in[3];
    const float* Wk = (const float*)d_in[4];
    const float* Wv = (const float*)d_in[5];
    const float* bv = (const float*)d_in[6];
    const float* Wo = (const float*)d_in[7];
    const float* bo = (const float*)d_in[8];
    float* out = (float*)d_out;

    __half *qc, *kc, *vc, *wc, *qh, *kh, *vh, *ah;
    cudaGetSymbolAddress((void**)&qc, g_qc);
    cudaGetSymbolAddress((void**)&kc, g_kc);
    cudaGetSymbolAddress((void**)&vc, g_vc);
    cudaGetSymbolAddress((void**)&wc, g_wc);
    cudaGetSymbolAddress((void**)&qh, g_qh);
    cudaGetSymbolAddress((void**)&kh, g_kh);
    cudaGetSymbolAddress((void**)&vh, g_vh);
    cudaGetSymbolAddress((void**)&ah, g_ah);

    cudaFuncSetAttribute(gemm_mma, cudaFuncAttributeMaxDynamicSharedMemorySize,
                         GEMM_SMEM);
    cudaFuncSetAttribute(attn_mma, cudaFuncAttributeMaxDynamicSharedMemorySize,
                         ATTN_SMEM);

    // ---- fp16 conversion prepass (one launch) ----
    round_h_all<<<(TOT8 + 255) / 256, 256>>>(
        (const float4*)q, (const float4*)k, (const float4*)v,
        (const float4*)Wq, (const float4*)Wk, (const float4*)Wv, (const float4*)Wo,
        qc, kc, vc, wc);

    // ---- fused Q/K/V projections (fp16 out) ----
    const dim3 ggrd3(M_ / GTM, E_ / GTN, 3);   // (32, 8, 3)
    gemm_mma<<<ggrd3, 256, GEMM_SMEM>>>(qc, kc, vc,
                                        wc, wc + (size_t)E_ * E_, wc + 2 * (size_t)E_ * E_,
                                        nullptr,
                                        qh, kh, vh,
                                        nullptr, nullptr, bv);

    // ---- attention ----
    const dim3 agrd(S_ / AQ, B_ * H_);         // (16, 32)
    attn_mma<<<agrd, 256, ATTN_SMEM>>>(qh, kh, vh, ah);

    // ---- output projection (fp32 out + bias) ----
    const dim3 ggrd1(M_ / GTM, E_ / GTN, 1);   // (32, 8)
    gemm_mma<<<ggrd1, 256, GEMM_SMEM>>>(ah, ah, ah,
                                        wc + 3 * (size_t)E_ * E_, nullptr, nullptr,
                                        out,
                                        nullptr, nullptr, nullptr,
                                        bo, bo, bo);
}

// round 9
// speedup vs baseline: 8.0428x; 1.0068x over previous
#include <cuda_runtime.h>
#include <cuda_fp16.h>
#include <cstdint>

// Problem constants
#define B_   2
#define S_   2048
#define E_   1024
#define H_   16
#define HD_  64
#define M_   (B_ * S_)   // 4096 flattened rows

// Scratch (fp16)
__device__ __half g_qc[M_ * E_];
__device__ __half g_kc[M_ * E_];
__device__ __half g_vc[M_ * E_];
__device__ __half g_wc[4 * E_ * E_];
__device__ __half g_qh[M_ * E_];
__device__ __half g_kh[M_ * E_];
__device__ __half g_vh[M_ * E_];
__device__ __half g_ah[M_ * E_];

// ===========================================================================
// Helpers
// ===========================================================================
__device__ __forceinline__ uint32_t smem_u32(const void* p) {
    uint32_t a;
    asm("{ .reg .u64 t; cvta.to.shared.u64 t, %1; cvt.u32.u64 %0, t; }"
        : "=r"(a) : "l"(p));
    return a;
}

__device__ __forceinline__ void cp_async16(uint32_t dst, const void* src) {
    asm volatile("cp.async.cg.shared.global [%0], [%1], 16;"
                 :: "r"(dst), "l"(src) : "memory");
}
#define CP_COMMIT() asm volatile("cp.async.commit_group;" ::: "memory")
#define CP_WAIT1()  asm volatile("cp.async.wait_group 1;" ::: "memory")

__device__ __forceinline__ void mma_f16(float* d, const uint32_t* a, const uint32_t* b) {
    asm volatile(
        "mma.sync.aligned.m16n8k16.row.col.f32.f16.f16.f32 "
        "{%0,%1,%2,%3}, {%4,%5,%6,%7}, {%8,%9}, {%0,%1,%2,%3};"
        : "+f"(d[0]), "+f"(d[1]), "+f"(d[2]), "+f"(d[3])
        : "r"(a[0]), "r"(a[1]), "r"(a[2]), "r"(a[3]), "r"(b[0]), "r"(b[1]));
}

__device__ __forceinline__ void ldsm4(uint32_t* r, uint32_t addr) {
    asm volatile("ldmatrix.sync.aligned.m8n8.x4.shared.b16 {%0,%1,%2,%3}, [%4];"
                 : "=r"(r[0]), "=r"(r[1]), "=r"(r[2]), "=r"(r[3]) : "r"(addr));
}
__device__ __forceinline__ void ldsm4t(uint32_t* r, uint32_t addr) {
    asm volatile("ldmatrix.sync.aligned.m8n8.x4.trans.shared.b16 {%0,%1,%2,%3}, [%4];"
                 : "=r"(r[0]), "=r"(r[1]), "=r"(r[2]), "=r"(r[3]) : "r"(addr));
}

__device__ __forceinline__ uint32_t h2pack(float a, float b) {
    __half2 h = __floats2half2_rn(a, b);
    return *(uint32_t*)&h;
}

// ===========================================================================
// fp32 -> fp16 conversion prepass (one launch; groups of 8 floats)
// ===========================================================================
#define ACT8 (M_ * E_ / 8)
#define W8   (E_ * E_ / 8)
#define TOT8 (3 * ACT8 + 4 * W8)

__global__ __launch_bounds__(256) void round_h_all(
    const float4* __restrict__ q, const float4* __restrict__ k,
    const float4* __restrict__ v,
    const float4* __restrict__ Wq, const float4* __restrict__ Wk,
    const float4* __restrict__ Wv, const float4* __restrict__ Wo,
    __half* __restrict__ qc, __half* __restrict__ kc,
    __half* __restrict__ vc, __half* __restrict__ wc)
{
    const long i = (long)blockIdx.x * 256 + threadIdx.x;
    if (i >= TOT8) return;
    const float4* s; __half* d; long off;
    if (i < ACT8)            { s = q; d = qc; off = i; }
    else if (i < 2L * ACT8)  { s = k; d = kc; off = i - ACT8; }
    else if (i < 3L * ACT8)  { s = v; d = vc; off = i - 2L * ACT8; }
    else {
        const long j = i - 3L * ACT8;
        s = (j < W8) ? Wq : (j < 2 * W8) ? Wk : (j < 3 * W8) ? Wv : Wo;
        d = wc + (j / W8) * (E_ * (long)E_);
        off = j % W8;
    }
    float4 u = s[2 * off], w = s[2 * off + 1];
    uint4 o;
    o.x = h2pack(u.x, u.y); o.y = h2pack(u.z, u.w);
    o.z = h2pack(w.x, w.y); o.w = h2pack(w.z, w.w);
    *(uint4*)(d + off * 8) = o;
}

// ===========================================================================
// mma.sync fp16 GEMM:  C[M,1024] = A[M,1024] @ W[1024,1024]^T (+ bias)
// CTA 128x128, 4 warps (2x2), warp tile 64x64, K-chunk 64 halves, 3-stage
// cp.async, ldmatrix.x4. 2 CTAs/SM. Output fp16 (Ch) or fp32 (Cf).
// ===========================================================================
#define GTM   128
#define GTN   128
#define GTK   64
#define NCH   (E_ / GTK)                  // 16
#define STRB  144
#define AB_   (GTM * STRB)                // 18432
#define STG_BYTES (AB_ + GTN * STRB)      // 36864
#define NSTG  3
#define GEMM_SMEM (NSTG * STG_BYTES)      // 110592

__global__ __launch_bounds__(128, 2) void gemm_mma(
    const __half* __restrict__ A0, const __half* __restrict__ A1,
    const __half* __restrict__ A2,
    const __half* __restrict__ W0, const __half* __restrict__ W1,
    const __half* __restrict__ W2,
    float* __restrict__ Cf,
    __half* __restrict__ Ch0, __half* __restrict__ Ch1, __half* __restrict__ Ch2,
    const float* __restrict__ b0, const float* __restrict__ b1,
    const float* __restrict__ b2)
{
    extern __shared__ char smem[];
    const int tid  = threadIdx.x;
    const int lane = tid & 31;
    const int wid  = tid >> 5;
    const int wm   = wid & 1;    // 2 row-slices of 64
    const int wn   = wid >> 1;   // 2 col-slices of 64

    const int z = blockIdx.z;
    const __half* A = (z == 0) ? A0 : (z == 1) ? A1 : A2;
    const __half* W = (z == 0) ? W0 : (z == 1) ? W1 : W2;
    __half* Ch = (z == 0) ? Ch0 : (z == 1) ? Ch1 : Ch2;
    const float* bias = (z == 0) ? b0 : (z == 1) ? b1 : b2;

    const int m0 = blockIdx.x * GTM;
    const int n0 = blockIdx.y * GTN;
    const uint32_t sb = smem_u32(smem);

    uint32_t aoff[4], boff[4];
    #pragma unroll
    for (int ii = 0; ii < 4; ii++)
        aoff[ii] = (wm * 64 + ii * 16 + (lane & 15)) * STRB + (lane >> 4) * 16;
    #pragma unroll
    for (int jp = 0; jp < 4; jp++)
        boff[jp] = AB_ + (wn * 64 + jp * 16 + ((lane >> 4) << 3) + (lane & 7)) * STRB
                 + ((lane >> 3) & 1) * 16;

    float acc[4][8][4] = {};

    auto load_chunk = [&](int ch, int stg) {
        const int k0 = ch * GTK;
        const uint32_t as = sb + stg * STG_BYTES;
        const uint32_t bs = as + AB_;
        #pragma unroll
        for (int it = 0; it < 8; it++) {
            const int idx = tid + it * 128;
            const int r = idx >> 3, c8 = idx & 7;
            cp_async16(as + r * STRB + c8 * 16,
                       A + (size_t)(m0 + r) * E_ + k0 + c8 * 8);
        }
        #pragma unroll
        for (int it = 0; it < 8; it++) {
            const int idx = tid + it * 128;
            const int r = idx >> 3, c8 = idx & 7;
            cp_async16(bs + r * STRB + c8 * 16,
                       W + (size_t)(n0 + r) * E_ + k0 + c8 * 8);
        }
    };

    load_chunk(0, 0); CP_COMMIT();
    load_chunk(1, 1); CP_COMMIT();

    for (int i = 0; i < NCH; i++) {
        CP_WAIT1();
        __syncthreads();
        if (i + 2 < NCH) load_chunk(i + 2, (i + 2) % NSTG);
        CP_COMMIT();

        const uint32_t su = sb + (i % NSTG) * STG_BYTES;

        #pragma unroll
        for (int kk = 0; kk < 4; kk++) {     // 4 x k16 = 64 halves
            const uint32_t kb = su + kk * 32;
            uint32_t af[4][4], bf[4][4];
            #pragma unroll
            for (int ii = 0; ii < 4; ii++) ldsm4(af[ii], kb + aoff[ii]);
            #pragma unroll
            for (int jp = 0; jp < 4; jp++) ldsm4(bf[jp], kb + boff[jp]);
            #pragma unroll
            for (int ii = 0; ii < 4; ii++)
                #pragma unroll
                for (int jp = 0; jp < 4; jp++) {
                    mma_f16(acc[ii][2 * jp],     af[ii], &bf[jp][0]);
                    mma_f16(acc[ii][2 * jp + 1], af[ii], &bf[jp][2]);
                }
        }
    }

    const int g = lane >> 2;
    const int c = lane & 3;
    #pragma unroll
    for (int ii = 0; ii < 4; ii++) {
        const int r0 = m0 + wm * 64 + ii * 16 + g;
        #pragma unroll
        for (int jj = 0; jj < 8; jj++) {
            const int cc = n0 + wn * 64 + jj * 8 + 2 * c;
            float bx = 0.f, by = 0.f;
            if (bias) { bx = bias[cc]; by = bias[cc + 1]; }
            const float v00 = acc[ii][jj][0] + bx, v01 = acc[ii][jj][1] + by;
            const float v10 = acc[ii][jj][2] + bx, v11 = acc[ii][jj][3] + by;
            if (Ch) {
                *(uint32_t*)&Ch[(size_t)r0 * E_ + cc]       = h2pack(v00, v01);
                *(uint32_t*)&Ch[(size_t)(r0 + 8) * E_ + cc] = h2pack(v10, v11);
            } else {
                *(float2*)&Cf[(size_t)r0 * E_ + cc]       = make_float2(v00, v01);
                *(float2*)&Cf[(size_t)(r0 + 8) * E_ + cc] = make_float2(v10, v11);
            }
        }
    }
}

// ===========================================================================
// fp16 tensor-core flash attention, strict-causal with (0,0) exception.
// CTA = (b,h) x 128 q-rows; 4 warps x 32 rows; K/V blocks of 64, 2 CTAs/SM.
// P in registers (D-frag -> A-frag repack); V via ldmatrix.trans.
// ===========================================================================
#define AQ    128
#define AK    64
#define QBYTES (AQ * 144)                     // 18432
#define KVBYTES (AK * 144)                    // 9216
#define OFF_K  QBYTES
#define OFF_V  (OFF_K + 2 * KVBYTES)
#define ATTN_SMEM (OFF_V + 2 * KVBYTES)       // 55296

__global__ __launch_bounds__(128, 2) void attn_mma(
    const __half* __restrict__ QH, const __half* __restrict__ KH,
    const __half* __restrict__ VH, __half* __restrict__ AH)
{
    extern __shared__ char smc[];
    const int tid  = threadIdx.x;
    const int lane = tid & 31;
    const int w    = tid >> 5;
    const int g    = lane >> 2;
    const int c    = lane & 3;
    const int qi   = (int)(gridDim.x - 1) - (int)blockIdx.x;  // heavy tiles first
    const int bh   = blockIdx.y;
    const int b    = bh >> 4;
    const int h    = bh & 15;
    const int qbase = qi * AQ;
    const size_t rb = (size_t)b * S_ * E_ + (size_t)h * HD_;

    const uint32_t sb = smem_u32(smc);

    // ---- load Q tile (128 x 64 halves) ----
    #pragma unroll
    for (int it = 0; it < 8; it++) {
        const int idx = tid + it * 128;       // 1024 x 16B
        const int r = idx >> 3, c8 = idx & 7;
        uint4 v = *(const uint4*)&QH[rb + (size_t)(qbase + r) * E_ + c8 * 8];
        *(uint4*)(smc + r * 144 + c8 * 16) = v;
    }
    __syncthreads();

    // ---- Q fragments: 2 m16 x 4 k16 ----
    uint32_t qf[2][4][4];
    #pragma unroll
    for (int ii = 0; ii < 2; ii++)
        #pragma unroll
        for (int kk = 0; kk < 4; kk++)
            ldsm4(qf[ii][kk], sb + (w * 32 + ii * 16 + (lane & 15)) * 144
                              + kk * 32 + (lane >> 4) * 16);
    __syncthreads();

    float o[2][8][4] = {};
    float mr[2][2] = {{-1e30f, -1e30f}, {-1e30f, -1e30f}};
    float lr[2][2] = {};
    const int nb = 2 * qi + 2;
    const int wmin = qbase + w * 32;
    const int wmax = wmin + 31;

    uint32_t koff[4], voff[4];
    #pragma unroll
    for (int jp = 0; jp < 4; jp++)
        koff[jp] = (jp * 16 + ((lane >> 4) << 3) + (lane & 7)) * 144
                 + ((lane >> 3) & 1) * 16;
    {
        const int qd = lane >> 3;
        #pragma unroll
        for (int jp = 0; jp < 4; jp++)
            voff[jp] = (((qd & 1) << 3) + (lane & 7)) * 144
                     + jp * 32 + ((qd >> 1) << 4);
    }

    auto loadKV = [&](int kb, int stg) {
        const int t0 = kb * AK;
        const uint32_t ks = sb + OFF_K + stg * KVBYTES;
        const uint32_t vs = sb + OFF_V + stg * KVBYTES;
        #pragma unroll
        for (int it = 0; it < 4; it++) {
            const int idx = tid + it * 128;   // 512 x 16B each
            const int r = idx >> 3, c8 = idx & 7;
            cp_async16(ks + r * 144 + c8 * 16,
                       &KH[rb + (size_t)(t0 + r) * E_ + c8 * 8]);
            cp_async16(vs + r * 144 + c8 * 16,
                       &VH[rb + (size_t)(t0 + r) * E_ + c8 * 8]);
        }
    };

    loadKV(0, 0); CP_COMMIT();

    for (int kb = 0; kb < nb; kb++) {
        const int stg = kb & 1;
        const int t0  = kb * AK;
        if (kb + 1 < nb) loadKV(kb + 1, stg ^ 1);
        CP_COMMIT();
        CP_WAIT1();
        __syncthreads();

        if (t0 <= wmax) {
            const uint32_t ks = sb + OFF_K + stg * KVBYTES;
            const uint32_t vs = sb + OFF_V + stg * KVBYTES;

            // ---- S = Q @ K^T ----
            float sc[2][8][4] = {};
            #pragma unroll
            for (int kk = 0; kk < 4; kk++) {
                uint32_t kf[4][4];
                #pragma unroll
                for (int jp = 0; jp < 4; jp++) ldsm4(kf[jp], ks + koff[jp] + kk * 32);
                #pragma unroll
                for (int ii = 0; ii < 2; ii++)
                    #pragma unroll
                    for (int jp = 0; jp < 4; jp++) {
                        mma_f16(sc[ii][2 * jp],     qf[ii][kk], &kf[jp][0]);
                        mma_f16(sc[ii][2 * jp + 1], qf[ii][kk], &kf[jp][2]);
                    }
            }

            // ---- scale + causal mask + online softmax + rescale O ----
            const bool needmask = (t0 + AK - 1) >= wmin;
            #pragma unroll
            for (int ii = 0; ii < 2; ii++) {
                const int qrow0 = qbase + w * 32 + ii * 16 + g;
                #pragma unroll
                for (int jj = 0; jj < 8; jj++) {
                    sc[ii][jj][0] *= 0.125f; sc[ii][jj][1] *= 0.125f;
                    sc[ii][jj][2] *= 0.125f; sc[ii][jj][3] *= 0.125f;
                    if (needmask) {
                        const int cg = t0 + jj * 8 + 2 * c;
                        const int r0 = qrow0, r1 = qrow0 + 8;
                        if (!((cg     < r0) || (r0 == 0 && cg == 0)))     sc[ii][jj][0] = -1e30f;
                        if (!((cg + 1 < r0) || (r0 == 0 && cg + 1 == 0))) sc[ii][jj][1] = -1e30f;
                        if (!(cg     < r1)) sc[ii][jj][2] = -1e30f;
                        if (!(cg + 1 < r1)) sc[ii][jj][3] = -1e30f;
                    }
                }

                float mx0 = -1e30f, mx1 = -1e30f;
                #pragma unroll
                for (int jj = 0; jj < 8; jj++) {
                    mx0 = fmaxf(mx0, fmaxf(sc[ii][jj][0], sc[ii][jj][1]));
                    mx1 = fmaxf(mx1, fmaxf(sc[ii][jj][2], sc[ii][jj][3]));
                }
                mx0 = fmaxf(mx0, __shfl_xor_sync(0xffffffffu, mx0, 1));
                mx0 = fmaxf(mx0, __shfl_xor_sync(0xffffffffu, mx0, 2));
                mx1 = fmaxf(mx1, __shfl_xor_sync(0xffffffffu, mx1, 1));
                mx1 = fmaxf(mx1, __shfl_xor_sync(0xffffffffu, mx1, 2));
                const float mn0 = fmaxf(mr[ii][0], mx0), mn1 = fmaxf(mr[ii][1], mx1);
                const float a0 = __expf(mr[ii][0] - mn0), a1 = __expf(mr[ii][1] - mn1);
                float s0 = 0.f, s1 = 0.f;
                #pragma unroll
                for (int jj = 0; jj < 8; jj++) {
                    sc[ii][jj][0] = __expf(sc[ii][jj][0] - mn0);
                    sc[ii][jj][1] = __expf(sc[ii][jj][1] - mn0);
                    sc[ii][jj][2] = __expf(sc[ii][jj][2] - mn1);
                    sc[ii][jj][3] = __expf(sc[ii][jj][3] - mn1);
                    s0 += sc[ii][jj][0] + sc[ii][jj][1];
                    s1 += sc[ii][jj][2] + sc[ii][jj][3];
                }
                s0 += __shfl_xor_sync(0xffffffffu, s0, 1);
                s0 += __shfl_xor_sync(0xffffffffu, s0, 2);
                s1 += __shfl_xor_sync(0xffffffffu, s1, 1);
                s1 += __shfl_xor_sync(0xffffffffu, s1, 2);
                lr[ii][0] = lr[ii][0] * a0 + s0; lr[ii][1] = lr[ii][1] * a1 + s1;
                mr[ii][0] = mn0; mr[ii][1] = mn1;
                #pragma unroll
                for (int jj = 0; jj < 8; jj++) {
                    o[ii][jj][0] *= a0; o[ii][jj][1] *= a0;
                    o[ii][jj][2] *= a1; o[ii][jj][3] *= a1;
                }
            }

            // ---- O += P @ V  (P repacked from D-frags; V via ldmatrix.trans) ----
            #pragma unroll
            for (int kk = 0; kk < 4; kk++) {
                uint32_t pf[2][4];
                #pragma unroll
                for (int ii = 0; ii < 2; ii++) {
                    pf[ii][0] = h2pack(sc[ii][2 * kk][0],     sc[ii][2 * kk][1]);
                    pf[ii][1] = h2pack(sc[ii][2 * kk][2],     sc[ii][2 * kk][3]);
                    pf[ii][2] = h2pack(sc[ii][2 * kk + 1][0], sc[ii][2 * kk + 1][1]);
                    pf[ii][3] = h2pack(sc[ii][2 * kk + 1][2], sc[ii][2 * kk + 1][3]);
                }
                uint32_t vf[4][4];
                #pragma unroll
                for (int jp = 0; jp < 4; jp++)
                    ldsm4t(vf[jp], vs + voff[jp] + kk * 16 * 144);
                #pragma unroll
                for (int ii = 0; ii < 2; ii++)
                    #pragma unroll
                    for (int jp = 0; jp < 4; jp++) {
                        mma_f16(o[ii][2 * jp],     pf[ii], &vf[jp][0]);
                        mma_f16(o[ii][2 * jp + 1], pf[ii], &vf[jp][2]);
                    }
            }
        }
        __syncthreads();
    }

    // ---- epilogue: normalize, convert to fp16 for Wo GEMM ----
    #pragma unroll
    for (int ii = 0; ii < 2; ii++) {
        const int qrow0 = qbase + w * 32 + ii * 16 + g;
        const float il0 = 1.f / lr[ii][0], il1 = 1.f / lr[ii][1];
        #pragma unroll
        for (int jj = 0; jj < 8; jj++) {
            const int col = jj * 8 + 2 * c;
            *(uint32_t*)&AH[rb + (size_t)qrow0 * E_ + col] =
                h2pack(o[ii][jj][0] * il0, o[ii][jj][1] * il0);
            *(uint32_t*)&AH[rb + (size_t)(qrow0 + 8) * E_ + col] =
                h2pack(o[ii][jj][2] * il1, o[ii][jj][3] * il1);
        }
    }
}

// ===========================================================================
extern "C" void kernel_launch(void* const* d_in, const int* in_sizes, int n_in,
                              void* d_out, int out_size)
{
    const float* q  = (const float*)d_in[0];
    const float* k  = (const float*)d_in[1];
    const float* v  = (const float*)d_in[2];
    const float* Wq = (const float*)d_in[3];
    const float* Wk = (const float*)d_in[4];
    const float* Wv = (const float*)d_in[5];
    const float* bv = (const float*)d_in[6];
    const float* Wo = (const float*)d_in[7];
    const float* bo = (const float*)d_in[8];
    float* out = (float*)d_out;

    __half *qc, *kc, *vc, *wc, *qh, *kh, *vh, *ah;
    cudaGetSymbolAddress((void**)&qc, g_qc);
    cudaGetSymbolAddress((void**)&kc, g_kc);
    cudaGetSymbolAddress((void**)&vc, g_vc);
    cudaGetSymbolAddress((void**)&wc, g_wc);
    cudaGetSymbolAddress((void**)&qh, g_qh);
    cudaGetSymbolAddress((void**)&kh, g_kh);
    cudaGetSymbolAddress((void**)&vh, g_vh);
    cudaGetSymbolAddress((void**)&ah, g_ah);

    cudaFuncSetAttribute(gemm_mma, cudaFuncAttributeMaxDynamicSharedMemorySize,
                         GEMM_SMEM);
    cudaFuncSetAttribute(attn_mma, cudaFuncAttributeMaxDynamicSharedMemorySize,
                         ATTN_SMEM);

    // ---- fp16 conversion prepass (one launch) ----
    round_h_all<<<(TOT8 + 255) / 256, 256>>>(
        (const float4*)q, (const float4*)k, (const float4*)v,
        (const float4*)Wq, (const float4*)Wk, (const float4*)Wv, (const float4*)Wo,
        qc, kc, vc, wc);

    // ---- fused Q/K/V projections (fp16 out) ----
    const dim3 ggrd3(M_ / GTM, E_ / GTN, 3);   // (32, 8, 3)
    gemm_mma<<<ggrd3, 128, GEMM_SMEM>>>(qc, kc, vc,
                                        wc, wc + (size_t)E_ * E_, wc + 2 * (size_t)E_ * E_,
                                        nullptr,
                                        qh, kh, vh,
                                        nullptr, nullptr, bv);

    // ---- attention ----
    const dim3 agrd(S_ / AQ, B_ * H_);         // (16, 32)
    attn_mma<<<agrd, 128, ATTN_SMEM>>>(qh, kh, vh, ah);

    // ---- output projection (fp32 out + bias) ----
    const dim3 ggrd1(M_ / GTM, E_ / GTN, 1);   // (32, 8)
    gemm_mma<<<ggrd1, 128, GEMM_SMEM>>>(ah, ah, ah,
                                        wc + 3 * (size_t)E_ * E_, nullptr, nullptr,
                                        out,
                                        nullptr, nullptr, nullptr,
                                        bo, bo, bo);
}